// round 2
// baseline (speedup 1.0000x reference)
#include <cuda_runtime.h>
#include <math.h>

#define S 2048
#define D 1024
#define NH 8
#define NKV 2
#define HD 128
#define WS 64
#define NE 16
#define HDIM 512
#define NA (S*2)

// ---------------- scratch (static device globals; no allocation) ------------
__device__ float g_h[S*D];
__device__ float g_q[S*D];
__device__ float g_k[S*NKV*HD];
__device__ float g_v[S*NKV*HD];
__device__ float g_attn[S*D];
__device__ float g_x1[S*D];
__device__ float g_h2[S*D];
__device__ float g_probs[S*NE];
__device__ float g_topw[S*2];
__device__ int   g_topi[S*2];
__device__ int   g_cnt[NE];
__device__ int   g_off[NE];
__device__ int   g_cur[NE];
__device__ int   g_atok[NA];
__device__ float g_aw[NA];
__device__ int   g_tslot[S*2];
__device__ float g_hmid[NA*HDIM];
__device__ float g_y[NA*D];
__device__ float g_colsum[NE];

// ---------------- RMSNorm: one block per row, 256 threads x float4 ----------
__global__ void rmsnorm_kernel(const float* __restrict__ x,
                               const float* __restrict__ w,
                               float* __restrict__ o) {
    int row = blockIdx.x;
    int tid = threadIdx.x;
    const float4* x4 = (const float4*)(x + (size_t)row * D);
    float4 v = x4[tid];
    float ss = v.x*v.x + v.y*v.y + v.z*v.z + v.w*v.w;
    __shared__ float red[8];
    #pragma unroll
    for (int s = 16; s; s >>= 1) ss += __shfl_xor_sync(0xffffffffu, ss, s);
    if ((tid & 31) == 0) red[tid >> 5] = ss;
    __syncthreads();
    if (tid < 32) {
        float t = (tid < 8) ? red[tid] : 0.f;
        #pragma unroll
        for (int s = 4; s; s >>= 1) t += __shfl_xor_sync(0xffffffffu, t, s);
        if (tid == 0) red[0] = t;
    }
    __syncthreads();
    float r = rsqrtf(red[0] * (1.0f / (float)D) + 1e-6f);
    const float4* w4 = (const float4*)w;
    float4 wv = w4[tid];
    float4 out;
    out.x = v.x * r * wv.x; out.y = v.y * r * wv.y;
    out.z = v.z * r * wv.z; out.w = v.w * r * wv.w;
    ((float4*)(o + (size_t)row * D))[tid] = out;
}

// ---------------- generic tiled fp32 GEMM: C = A@B + bias [+resid][silu] ----
// A row-major [M,K], B row-major [K,N], C [M,N]. 128x128x16 tile, 256 thr, 8x8/thr.
// EPI: 0 = bias, 1 = bias+resid, 2 = bias+silu
#define BM 128
#define BN 128
#define BK 16

template<int EPI, bool GATHER, bool MOE>
__global__ void __launch_bounds__(256)
gemm_kernel(const float* __restrict__ A, const float* __restrict__ B,
            const float* __restrict__ bias, const float* __restrict__ resid,
            float* __restrict__ C, int M, int N, int K,
            const int* __restrict__ rowidx,
            const int* __restrict__ cnt, const int* __restrict__ off) {
    if (MOE) {
        int e = blockIdx.z;
        M = cnt[e];
        int o = off[e];
        B    += (size_t)e * K * N;
        bias += (size_t)e * N;
        C    += (size_t)o * N;
        if (GATHER) rowidx += o;
        else        A += (size_t)o * K;
    }
    int m0 = blockIdx.y * BM;
    if (m0 >= M) return;
    int n0 = blockIdx.x * BN;

    __shared__ float As[BK][BM + 4];
    __shared__ float Bs[BK][BN];

    int tid = threadIdx.x;
    int tx = tid & 15, ty = tid >> 4;

    int arow0 = tid >> 2;
    int arow1 = arow0 + 64;
    int ac = (tid & 3) * 4;
    bool v0 = (m0 + arow0) < M, v1 = (m0 + arow1) < M;
    const float *Ar0, *Ar1;
    {
        int r0 = m0 + arow0, r1 = m0 + arow1;
        int gidx0 = v0 ? (GATHER ? rowidx[r0] : r0) : 0;
        int gidx1 = v1 ? (GATHER ? rowidx[r1] : r1) : 0;
        Ar0 = A + (size_t)gidx0 * K;
        Ar1 = A + (size_t)gidx1 * K;
    }
    int brow = tid >> 5;
    int bc = (tid & 31) * 4;
    const float* Bp0 = B + (size_t)brow * N + n0 + bc;
    const float* Bp1 = B + (size_t)(brow + 8) * N + n0 + bc;

    float acc[8][8];
    #pragma unroll
    for (int i = 0; i < 8; i++)
        #pragma unroll
        for (int j = 0; j < 8; j++) acc[i][j] = 0.f;

    for (int k0 = 0; k0 < K; k0 += BK) {
        float4 a0 = v0 ? *(const float4*)(Ar0 + k0 + ac) : make_float4(0.f,0.f,0.f,0.f);
        float4 a1 = v1 ? *(const float4*)(Ar1 + k0 + ac) : make_float4(0.f,0.f,0.f,0.f);
        float4 b0 = *(const float4*)(Bp0 + (size_t)k0 * N);
        float4 b1 = *(const float4*)(Bp1 + (size_t)k0 * N);
        __syncthreads();
        As[ac+0][arow0] = a0.x; As[ac+1][arow0] = a0.y;
        As[ac+2][arow0] = a0.z; As[ac+3][arow0] = a0.w;
        As[ac+0][arow1] = a1.x; As[ac+1][arow1] = a1.y;
        As[ac+2][arow1] = a1.z; As[ac+3][arow1] = a1.w;
        *(float4*)&Bs[brow][bc]     = b0;
        *(float4*)&Bs[brow + 8][bc] = b1;
        __syncthreads();
        #pragma unroll
        for (int kk = 0; kk < BK; ++kk) {
            float ar[8], br[8];
            *(float4*)(ar)     = *(const float4*)&As[kk][ty * 4];
            *(float4*)(ar + 4) = *(const float4*)&As[kk][64 + ty * 4];
            *(float4*)(br)     = *(const float4*)&Bs[kk][tx * 4];
            *(float4*)(br + 4) = *(const float4*)&Bs[kk][64 + tx * 4];
            #pragma unroll
            for (int i = 0; i < 8; i++)
                #pragma unroll
                for (int j = 0; j < 8; j++)
                    acc[i][j] += ar[i] * br[j];
        }
    }

    #pragma unroll
    for (int i = 0; i < 8; i++) {
        int r = (i < 4) ? (ty * 4 + i) : (64 + ty * 4 + (i - 4));
        int rg = m0 + r;
        if (rg >= M) continue;
        #pragma unroll
        for (int half = 0; half < 2; ++half) {
            int cb = n0 + half * 64 + tx * 4;
            float vv[4];
            #pragma unroll
            for (int j = 0; j < 4; j++) {
                float t = acc[i][half * 4 + j] + bias[cb + j];
                if (EPI == 1) t += resid[(size_t)rg * N + cb + j];
                if (EPI == 2) t = t / (1.f + expf(-t));
                vv[j] = t;
            }
            *(float4*)&C[(size_t)rg * N + cb] = *(const float4*)vv;
        }
    }
}

// ---------------- sliding-window attention, 1 warp = 1 query row ------------
__global__ void attn_kernel(const float* __restrict__ sinkp) {
    int warp = threadIdx.x >> 5, lane = threadIdx.x & 31;
    int i = blockIdx.x * 8 + warp;
    int h = blockIdx.y;
    int kvh = h >> 2;  // NH/NKV = 4
    const float scale = 0.08838834764831845f;  // 1/sqrt(128)

    float qr[4];
    const float* qp = g_q + (size_t)i * D + h * HD;
    #pragma unroll
    for (int c = 0; c < 4; c++) qr[c] = qp[lane + 32 * c];

    int jstart = (i >= (WS - 1)) ? (i - (WS - 1)) : 0;
    int cnt = i - jstart + 1;

    float s0 = -1e30f, s1 = -1e30f;
    for (int jj = 0; jj < cnt; ++jj) {
        const float* kp = g_k + (size_t)(jstart + jj) * (NKV * HD) + kvh * HD;
        float p = qr[0]*kp[lane] + qr[1]*kp[lane+32] + qr[2]*kp[lane+64] + qr[3]*kp[lane+96];
        #pragma unroll
        for (int s = 16; s; s >>= 1) p += __shfl_xor_sync(0xffffffffu, p, s);
        p *= scale;
        if ((jj & 31) == lane) { if (jj < 32) s0 = p; else s1 = p; }
    }
    float sink = *sinkp;
    float m = fmaxf(s0, s1);
    #pragma unroll
    for (int s = 16; s; s >>= 1) m = fmaxf(m, __shfl_xor_sync(0xffffffffu, m, s));
    m = fmaxf(m, sink);
    float e0 = expf(s0 - m), e1 = expf(s1 - m);
    float dsum = e0 + e1;
    #pragma unroll
    for (int s = 16; s; s >>= 1) dsum += __shfl_xor_sync(0xffffffffu, dsum, s);
    dsum += expf(sink - m);
    float inv = 1.f / dsum;

    float o0 = 0.f, o1 = 0.f, o2 = 0.f, o3 = 0.f;
    for (int jj = 0; jj < cnt; ++jj) {
        float pv = (jj < 32) ? e0 : e1;
        float p = __shfl_sync(0xffffffffu, pv, jj & 31);
        const float* vp = g_v + (size_t)(jstart + jj) * (NKV * HD) + kvh * HD;
        o0 += p * vp[lane];      o1 += p * vp[lane + 32];
        o2 += p * vp[lane + 64]; o3 += p * vp[lane + 96];
    }
    float* op = g_attn + (size_t)i * D + h * HD;
    op[lane]      = o0 * inv; op[lane + 32] = o1 * inv;
    op[lane + 64] = o2 * inv; op[lane + 96] = o3 * inv;
}

// ---------------- router: 1 warp = 1 token ----------------------------------
__global__ void router_kernel(const float* __restrict__ rw, const float* __restrict__ rb) {
    int warp = threadIdx.x >> 5, lane = threadIdx.x & 31;
    int t = blockIdx.x * 8 + warp;
    float acc[NE];
    #pragma unroll
    for (int e = 0; e < NE; e++) acc[e] = 0.f;
    const float* xr = g_h2 + (size_t)t * D;
    for (int d = lane; d < D; d += 32) {
        float xv = xr[d];
        const float* rr = rw + d * NE;
        #pragma unroll
        for (int e = 0; e < NE; e++) acc[e] += xv * rr[e];
    }
    #pragma unroll
    for (int e = 0; e < NE; e++) {
        float a = acc[e];
        #pragma unroll
        for (int s = 16; s; s >>= 1) a += __shfl_xor_sync(0xffffffffu, a, s);
        acc[e] = a;
    }
    if (lane == 0) {
        float logit[NE]; float m = -1e30f;
        #pragma unroll
        for (int e = 0; e < NE; e++) { logit[e] = (acc[e] + rb[e]) * 10.f; m = fmaxf(m, logit[e]); }
        float pe[NE]; float ssum = 0.f;
        #pragma unroll
        for (int e = 0; e < NE; e++) { pe[e] = expf(logit[e] - m); ssum += pe[e]; }
        float invs = 1.f / ssum;
        #pragma unroll
        for (int e = 0; e < NE; e++) g_probs[t * NE + e] = pe[e] * invs;
        int i0 = 0; float v0 = logit[0];
        #pragma unroll
        for (int e = 1; e < NE; e++) if (logit[e] > v0) { v0 = logit[e]; i0 = e; }
        int i1 = -1; float v1 = -1e30f;
        #pragma unroll
        for (int e = 0; e < NE; e++) if (e != i0 && logit[e] > v1) { v1 = logit[e]; i1 = e; }
        float ex = expf(v1 - v0);
        float w0 = 1.f / (1.f + ex);
        g_topi[t*2] = i0; g_topi[t*2+1] = i1;
        g_topw[t*2] = w0; g_topw[t*2+1] = 1.f - w0;
        atomicAdd(&g_cnt[i0], 1); atomicAdd(&g_cnt[i1], 1);
    }
}

__global__ void zero_kernel() {
    int t = threadIdx.x;
    if (t < NE) { g_cnt[t] = 0; g_cur[t] = 0; }
}

__global__ void offsets_kernel() {
    if (threadIdx.x == 0) {
        int s = 0;
        for (int e = 0; e < NE; e++) { g_off[e] = s; s += g_cnt[e]; }
    }
}

__global__ void place_kernel() {
    int t = blockIdx.x * blockDim.x + threadIdx.x;
    if (t >= S) return;
    #pragma unroll
    for (int k2 = 0; k2 < 2; k2++) {
        int e = g_topi[t*2 + k2];
        int slot = g_off[e] + atomicAdd(&g_cur[e], 1);
        g_atok[slot] = t;
        g_aw[slot] = g_topw[t*2 + k2];
        g_tslot[t*2 + k2] = slot;
    }
}

__global__ void colsum_kernel() {
    int e = blockIdx.x; int tid = threadIdx.x;
    float s = 0.f;
    for (int t = tid; t < S; t += 256) s += g_probs[t * NE + e];
    __shared__ float red[256];
    red[tid] = s; __syncthreads();
    for (int st = 128; st; st >>= 1) { if (tid < st) red[tid] += red[tid + st]; __syncthreads(); }
    if (tid == 0) g_colsum[e] = red[0];
}

__global__ void combine_kernel(float* __restrict__ out) {
    int t = blockIdx.x; int c = threadIdx.x;
    int s0 = g_tslot[t*2], s1 = g_tslot[t*2+1];
    float w0 = g_aw[s0], w1 = g_aw[s1];
    const float4* x14 = (const float4*)(g_x1 + (size_t)t * D);
    const float4* y0  = (const float4*)(g_y + (size_t)s0 * D);
    const float4* y1  = (const float4*)(g_y + (size_t)s1 * D);
    float4 a = x14[c], b = y0[c], d2 = y1[c];
    float4 o;
    o.x = a.x + w0*b.x + w1*d2.x; o.y = a.y + w0*b.y + w1*d2.y;
    o.z = a.z + w0*b.z + w1*d2.z; o.w = a.w + w0*b.w + w1*d2.w;
    ((float4*)out)[(size_t)t * (D/4) + c] = o;
}

__global__ void aux_kernel(float* __restrict__ out, int out_size) {
    int tid = threadIdx.x;
    float v = (tid < NE) ? g_colsum[tid] * g_colsum[tid] : 0.f;
    #pragma unroll
    for (int s = 16; s; s >>= 1) v += __shfl_xor_sync(0xffffffffu, v, s);
    if (tid == 0) {
        float aux = v * (1.0f / (float)NE) * 1e-5f;
        for (int idx = S * D; idx < out_size; ++idx) out[idx] = aux;
    }
}

// ---------------- launch -----------------------------------------------------
extern "C" void kernel_launch(void* const* d_in, const int* in_sizes, int n_in,
                              void* d_out, int out_size) {
    const float* x    = (const float*)d_in[0];
    const float* n1w  = (const float*)d_in[1];
    const float* wq   = (const float*)d_in[2];
    const float* bq   = (const float*)d_in[3];
    const float* wk   = (const float*)d_in[4];
    const float* bk   = (const float*)d_in[5];
    const float* wv   = (const float*)d_in[6];
    const float* bv   = (const float*)d_in[7];
    const float* wo   = (const float*)d_in[8];
    const float* bo   = (const float*)d_in[9];
    const float* sink = (const float*)d_in[10];
    const float* n2w  = (const float*)d_in[11];
    const float* rw   = (const float*)d_in[12];
    const float* rb   = (const float*)d_in[13];
    const float* w1   = (const float*)d_in[14];
    const float* b1   = (const float*)d_in[15];
    const float* w2   = (const float*)d_in[16];
    const float* b2   = (const float*)d_in[17];
    float* out = (float*)d_out;

    void* p;
    cudaGetSymbolAddress(&p, g_h);    float* hB    = (float*)p;
    cudaGetSymbolAddress(&p, g_q);    float* qB    = (float*)p;
    cudaGetSymbolAddress(&p, g_k);    float* kB    = (float*)p;
    cudaGetSymbolAddress(&p, g_v);    float* vB    = (float*)p;
    cudaGetSymbolAddress(&p, g_attn); float* aB    = (float*)p;
    cudaGetSymbolAddress(&p, g_x1);   float* x1B   = (float*)p;
    cudaGetSymbolAddress(&p, g_h2);   float* h2B   = (float*)p;
    cudaGetSymbolAddress(&p, g_hmid); float* hmidB = (float*)p;
    cudaGetSymbolAddress(&p, g_y);    float* yB    = (float*)p;
    cudaGetSymbolAddress(&p, g_atok); int*   atokB = (int*)p;
    cudaGetSymbolAddress(&p, g_cnt);  int*   cntB  = (int*)p;
    cudaGetSymbolAddress(&p, g_off);  int*   offB  = (int*)p;

    // 1) RMSNorm1
    rmsnorm_kernel<<<S, 256>>>(x, n1w, hB);

    // 2) QKV projections
    gemm_kernel<0,false,false><<<dim3(8,16,1), 256>>>(hB, wq, bq, nullptr, qB, S, 1024, 1024, nullptr, nullptr, nullptr);
    gemm_kernel<0,false,false><<<dim3(2,16,1), 256>>>(hB, wk, bk, nullptr, kB, S,  256, 1024, nullptr, nullptr, nullptr);
    gemm_kernel<0,false,false><<<dim3(2,16,1), 256>>>(hB, wv, bv, nullptr, vB, S,  256, 1024, nullptr, nullptr, nullptr);

    // 3) sliding-window attention with sink
    attn_kernel<<<dim3(S/8, NH), 256>>>(sink);

    // 4) O-proj + residual
    gemm_kernel<1,false,false><<<dim3(8,16,1), 256>>>(aB, wo, bo, x, x1B, S, 1024, 1024, nullptr, nullptr, nullptr);

    // 5) RMSNorm2
    rmsnorm_kernel<<<S, 256>>>(x1B, n2w, h2B);

    // 6) router + grouping
    zero_kernel<<<1, 32>>>();
    router_kernel<<<S/8, 256>>>(rw, rb);
    offsets_kernel<<<1, 32>>>();
    place_kernel<<<8, 256>>>();
    colsum_kernel<<<NE, 256>>>();

    // 7) grouped MoE GEMMs (top-2 only)
    gemm_kernel<2,true, true><<<dim3(4,16,NE), 256>>>(h2B,   w1, b1, nullptr, hmidB, S,  512, 1024, atokB, cntB, offB);
    gemm_kernel<0,false,true><<<dim3(8,16,NE), 256>>>(hmidB, w2, b2, nullptr, yB,    S, 1024,  512, nullptr, cntB, offB);

    // 8) combine + residual, aux loss
    combine_kernel<<<S, 256>>>(out);
    aux_kernel<<<1, 32>>>(out, out_size);
}

// round 3
// speedup vs baseline: 1.0014x; 1.0014x over previous
#include <cuda_runtime.h>
#include <math.h>

#define S 2048
#define D 1024
#define NH 8
#define NKV 2
#define HD 128
#define WS 64
#define NE 16
#define HDIM 512
#define NA (S*2)

// ---------------- scratch (static device globals; no allocation) ------------
__device__ float g_h[S*D];
__device__ float g_q[S*D];
__device__ float g_k[S*NKV*HD];
__device__ float g_v[S*NKV*HD];
__device__ float g_attn[S*D];
__device__ float g_x1[S*D];
__device__ float g_h2[S*D];
__device__ float g_probs[S*NE];
__device__ float g_topw[S*2];
__device__ int   g_topi[S*2];
__device__ int   g_cnt[NE];
__device__ int   g_off[NE];
__device__ int   g_cur[NE];
__device__ int   g_atok[NA];
__device__ float g_aw[NA];
__device__ int   g_tslot[S*2];
__device__ float g_hmid[NA*HDIM];
__device__ float g_y[NA*D];
__device__ float g_colsum[NE];

// ---------------- RMSNorm: one block per row, 256 threads x float4 ----------
__global__ void rmsnorm_kernel(const float* __restrict__ x,
                               const float* __restrict__ w,
                               float* __restrict__ o) {
    int row = blockIdx.x;
    int tid = threadIdx.x;
    const float4* x4 = (const float4*)(x + (size_t)row * D);
    float4 v = x4[tid];
    float ss = v.x*v.x + v.y*v.y + v.z*v.z + v.w*v.w;
    __shared__ float red[8];
    #pragma unroll
    for (int s = 16; s; s >>= 1) ss += __shfl_xor_sync(0xffffffffu, ss, s);
    if ((tid & 31) == 0) red[tid >> 5] = ss;
    __syncthreads();
    if (tid < 32) {
        float t = (tid < 8) ? red[tid] : 0.f;
        #pragma unroll
        for (int s = 4; s; s >>= 1) t += __shfl_xor_sync(0xffffffffu, t, s);
        if (tid == 0) red[0] = t;
    }
    __syncthreads();
    float r = rsqrtf(red[0] * (1.0f / (float)D) + 1e-6f);
    const float4* w4 = (const float4*)w;
    float4 wv = w4[tid];
    float4 out;
    out.x = v.x * r * wv.x; out.y = v.y * r * wv.y;
    out.z = v.z * r * wv.z; out.w = v.w * r * wv.w;
    ((float4*)(o + (size_t)row * D))[tid] = out;
}

// ---------------- generic tiled fp32 GEMM: C = A@B + bias [+resid][silu] ----
// A row-major [M,K], B row-major [K,N], C [M,N]. 128x128x16 tile, 256 thr, 8x8/thr.
// EPI: 0 = bias, 1 = bias+resid, 2 = bias+silu
#define BM 128
#define BN 128
#define BK 16

template<int EPI, bool GATHER, bool MOE>
__global__ void __launch_bounds__(256)
gemm_kernel(const float* __restrict__ A, const float* __restrict__ B,
            const float* __restrict__ bias, const float* __restrict__ resid,
            float* __restrict__ C, int M, int N, int K,
            const int* __restrict__ rowidx,
            const int* __restrict__ cnt, const int* __restrict__ off) {
    if (MOE) {
        int e = blockIdx.z;
        M = cnt[e];
        int o = off[e];
        B    += (size_t)e * K * N;
        bias += (size_t)e * N;
        C    += (size_t)o * N;
        if (GATHER) rowidx += o;
        else        A += (size_t)o * K;
    }
    int m0 = blockIdx.y * BM;
    if (m0 >= M) return;
    int n0 = blockIdx.x * BN;

    __shared__ float As[BK][BM + 4];
    __shared__ float Bs[BK][BN];

    int tid = threadIdx.x;
    int tx = tid & 15, ty = tid >> 4;

    int arow0 = tid >> 2;
    int arow1 = arow0 + 64;
    int ac = (tid & 3) * 4;
    bool v0 = (m0 + arow0) < M, v1 = (m0 + arow1) < M;
    const float *Ar0, *Ar1;
    {
        int r0 = m0 + arow0, r1 = m0 + arow1;
        int gidx0 = v0 ? (GATHER ? rowidx[r0] : r0) : 0;
        int gidx1 = v1 ? (GATHER ? rowidx[r1] : r1) : 0;
        Ar0 = A + (size_t)gidx0 * K;
        Ar1 = A + (size_t)gidx1 * K;
    }
    int brow = tid >> 5;
    int bc = (tid & 31) * 4;
    const float* Bp0 = B + (size_t)brow * N + n0 + bc;
    const float* Bp1 = B + (size_t)(brow + 8) * N + n0 + bc;

    float acc[8][8];
    #pragma unroll
    for (int i = 0; i < 8; i++)
        #pragma unroll
        for (int j = 0; j < 8; j++) acc[i][j] = 0.f;

    for (int k0 = 0; k0 < K; k0 += BK) {
        float4 a0 = v0 ? *(const float4*)(Ar0 + k0 + ac) : make_float4(0.f,0.f,0.f,0.f);
        float4 a1 = v1 ? *(const float4*)(Ar1 + k0 + ac) : make_float4(0.f,0.f,0.f,0.f);
        float4 b0 = *(const float4*)(Bp0 + (size_t)k0 * N);
        float4 b1 = *(const float4*)(Bp1 + (size_t)k0 * N);
        __syncthreads();
        As[ac+0][arow0] = a0.x; As[ac+1][arow0] = a0.y;
        As[ac+2][arow0] = a0.z; As[ac+3][arow0] = a0.w;
        As[ac+0][arow1] = a1.x; As[ac+1][arow1] = a1.y;
        As[ac+2][arow1] = a1.z; As[ac+3][arow1] = a1.w;
        *(float4*)&Bs[brow][bc]     = b0;
        *(float4*)&Bs[brow + 8][bc] = b1;
        __syncthreads();
        #pragma unroll
        for (int kk = 0; kk < BK; ++kk) {
            float ar[8], br[8];
            *(float4*)(ar)     = *(const float4*)&As[kk][ty * 4];
            *(float4*)(ar + 4) = *(const float4*)&As[kk][64 + ty * 4];
            *(float4*)(br)     = *(const float4*)&Bs[kk][tx * 4];
            *(float4*)(br + 4) = *(const float4*)&Bs[kk][64 + tx * 4];
            #pragma unroll
            for (int i = 0; i < 8; i++)
                #pragma unroll
                for (int j = 0; j < 8; j++)
                    acc[i][j] += ar[i] * br[j];
        }
    }

    #pragma unroll
    for (int i = 0; i < 8; i++) {
        int r = (i < 4) ? (ty * 4 + i) : (64 + ty * 4 + (i - 4));
        int rg = m0 + r;
        if (rg >= M) continue;
        #pragma unroll
        for (int half = 0; half < 2; ++half) {
            int cb = n0 + half * 64 + tx * 4;
            float vv[4];
            #pragma unroll
            for (int j = 0; j < 4; j++) {
                float t = acc[i][half * 4 + j] + bias[cb + j];
                if (EPI == 1) t += resid[(size_t)rg * N + cb + j];
                if (EPI == 2) t = t / (1.f + expf(-t));
                vv[j] = t;
            }
            *(float4*)&C[(size_t)rg * N + cb] = *(const float4*)vv;
        }
    }
}

// ---------------- sliding-window attention, 1 warp = 1 query row ------------
__global__ void attn_kernel(const float* __restrict__ sinkp) {
    int warp = threadIdx.x >> 5, lane = threadIdx.x & 31;
    int i = blockIdx.x * 8 + warp;
    int h = blockIdx.y;
    int kvh = h >> 2;  // NH/NKV = 4
    const float scale = 0.08838834764831845f;  // 1/sqrt(128)

    float qr[4];
    const float* qp = g_q + (size_t)i * D + h * HD;
    #pragma unroll
    for (int c = 0; c < 4; c++) qr[c] = qp[lane + 32 * c];

    int jstart = (i >= (WS - 1)) ? (i - (WS - 1)) : 0;
    int cnt = i - jstart + 1;

    float s0 = -1e30f, s1 = -1e30f;
    for (int jj = 0; jj < cnt; ++jj) {
        const float* kp = g_k + (size_t)(jstart + jj) * (NKV * HD) + kvh * HD;
        float p = qr[0]*kp[lane] + qr[1]*kp[lane+32] + qr[2]*kp[lane+64] + qr[3]*kp[lane+96];
        #pragma unroll
        for (int s = 16; s; s >>= 1) p += __shfl_xor_sync(0xffffffffu, p, s);
        p *= scale;
        if ((jj & 31) == lane) { if (jj < 32) s0 = p; else s1 = p; }
    }
    float sink = *sinkp;
    float m = fmaxf(s0, s1);
    #pragma unroll
    for (int s = 16; s; s >>= 1) m = fmaxf(m, __shfl_xor_sync(0xffffffffu, m, s));
    m = fmaxf(m, sink);
    float e0 = expf(s0 - m), e1 = expf(s1 - m);
    float dsum = e0 + e1;
    #pragma unroll
    for (int s = 16; s; s >>= 1) dsum += __shfl_xor_sync(0xffffffffu, dsum, s);
    dsum += expf(sink - m);
    float inv = 1.f / dsum;

    float o0 = 0.f, o1 = 0.f, o2 = 0.f, o3 = 0.f;
    for (int jj = 0; jj < cnt; ++jj) {
        float pv = (jj < 32) ? e0 : e1;
        float p = __shfl_sync(0xffffffffu, pv, jj & 31);
        const float* vp = g_v + (size_t)(jstart + jj) * (NKV * HD) + kvh * HD;
        o0 += p * vp[lane];      o1 += p * vp[lane + 32];
        o2 += p * vp[lane + 64]; o3 += p * vp[lane + 96];
    }
    float* op = g_attn + (size_t)i * D + h * HD;
    op[lane]      = o0 * inv; op[lane + 32] = o1 * inv;
    op[lane + 64] = o2 * inv; op[lane + 96] = o3 * inv;
}

// ---------------- router: 1 warp = 1 token ----------------------------------
__global__ void router_kernel(const float* __restrict__ rw, const float* __restrict__ rb) {
    int warp = threadIdx.x >> 5, lane = threadIdx.x & 31;
    int t = blockIdx.x * 8 + warp;
    float acc[NE];
    #pragma unroll
    for (int e = 0; e < NE; e++) acc[e] = 0.f;
    const float* xr = g_h2 + (size_t)t * D;
    for (int d = lane; d < D; d += 32) {
        float xv = xr[d];
        const float* rr = rw + d * NE;
        #pragma unroll
        for (int e = 0; e < NE; e++) acc[e] += xv * rr[e];
    }
    #pragma unroll
    for (int e = 0; e < NE; e++) {
        float a = acc[e];
        #pragma unroll
        for (int s = 16; s; s >>= 1) a += __shfl_xor_sync(0xffffffffu, a, s);
        acc[e] = a;
    }
    if (lane == 0) {
        float logit[NE]; float m = -1e30f;
        #pragma unroll
        for (int e = 0; e < NE; e++) { logit[e] = (acc[e] + rb[e]) * 10.f; m = fmaxf(m, logit[e]); }
        float pe[NE]; float ssum = 0.f;
        #pragma unroll
        for (int e = 0; e < NE; e++) { pe[e] = expf(logit[e] - m); ssum += pe[e]; }
        float invs = 1.f / ssum;
        #pragma unroll
        for (int e = 0; e < NE; e++) g_probs[t * NE + e] = pe[e] * invs;
        int i0 = 0; float v0 = logit[0];
        #pragma unroll
        for (int e = 1; e < NE; e++) if (logit[e] > v0) { v0 = logit[e]; i0 = e; }
        int i1 = -1; float v1 = -1e30f;
        #pragma unroll
        for (int e = 0; e < NE; e++) if (e != i0 && logit[e] > v1) { v1 = logit[e]; i1 = e; }
        float ex = expf(v1 - v0);
        float w0 = 1.f / (1.f + ex);
        g_topi[t*2] = i0; g_topi[t*2+1] = i1;
        g_topw[t*2] = w0; g_topw[t*2+1] = 1.f - w0;
        atomicAdd(&g_cnt[i0], 1); atomicAdd(&g_cnt[i1], 1);
    }
}

__global__ void zero_kernel() {
    int t = threadIdx.x;
    if (t < NE) { g_cnt[t] = 0; g_cur[t] = 0; }
}

__global__ void offsets_kernel() {
    if (threadIdx.x == 0) {
        int s = 0;
        for (int e = 0; e < NE; e++) { g_off[e] = s; s += g_cnt[e]; }
    }
}

__global__ void place_kernel() {
    int t = blockIdx.x * blockDim.x + threadIdx.x;
    if (t >= S) return;
    #pragma unroll
    for (int k2 = 0; k2 < 2; k2++) {
        int e = g_topi[t*2 + k2];
        int slot = g_off[e] + atomicAdd(&g_cur[e], 1);
        g_atok[slot] = t;
        g_aw[slot] = g_topw[t*2 + k2];
        g_tslot[t*2 + k2] = slot;
    }
}

__global__ void colsum_kernel() {
    int e = blockIdx.x; int tid = threadIdx.x;
    float s = 0.f;
    for (int t = tid; t < S; t += 256) s += g_probs[t * NE + e];
    __shared__ float red[256];
    red[tid] = s; __syncthreads();
    for (int st = 128; st; st >>= 1) { if (tid < st) red[tid] += red[tid + st]; __syncthreads(); }
    if (tid == 0) g_colsum[e] = red[0];
}

__global__ void combine_kernel(float* __restrict__ out) {
    int t = blockIdx.x; int c = threadIdx.x;
    int s0 = g_tslot[t*2], s1 = g_tslot[t*2+1];
    float w0 = g_aw[s0], w1 = g_aw[s1];
    const float4* x14 = (const float4*)(g_x1 + (size_t)t * D);
    const float4* y0  = (const float4*)(g_y + (size_t)s0 * D);
    const float4* y1  = (const float4*)(g_y + (size_t)s1 * D);
    float4 a = x14[c], b = y0[c], d2 = y1[c];
    float4 o;
    o.x = a.x + w0*b.x + w1*d2.x; o.y = a.y + w0*b.y + w1*d2.y;
    o.z = a.z + w0*b.z + w1*d2.z; o.w = a.w + w0*b.w + w1*d2.w;
    ((float4*)out)[(size_t)t * (D/4) + c] = o;
}

__global__ void aux_kernel(float* __restrict__ out, int out_size) {
    int tid = threadIdx.x;
    float v = (tid < NE) ? g_colsum[tid] * g_colsum[tid] : 0.f;
    #pragma unroll
    for (int s = 16; s; s >>= 1) v += __shfl_xor_sync(0xffffffffu, v, s);
    if (tid == 0) {
        float aux = v * (1.0f / (float)NE) * 1e-5f;
        for (int idx = S * D; idx < out_size; ++idx) out[idx] = aux;
    }
}

// ---------------- launch -----------------------------------------------------
extern "C" void kernel_launch(void* const* d_in, const int* in_sizes, int n_in,
                              void* d_out, int out_size) {
    const float* x    = (const float*)d_in[0];
    const float* n1w  = (const float*)d_in[1];
    const float* wq   = (const float*)d_in[2];
    const float* bq   = (const float*)d_in[3];
    const float* wk   = (const float*)d_in[4];
    const float* bk   = (const float*)d_in[5];
    const float* wv   = (const float*)d_in[6];
    const float* bv   = (const float*)d_in[7];
    const float* wo   = (const float*)d_in[8];
    const float* bo   = (const float*)d_in[9];
    const float* sink = (const float*)d_in[10];
    const float* n2w  = (const float*)d_in[11];
    const float* rw   = (const float*)d_in[12];
    const float* rb   = (const float*)d_in[13];
    const float* w1   = (const float*)d_in[14];
    const float* b1   = (const float*)d_in[15];
    const float* w2   = (const float*)d_in[16];
    const float* b2   = (const float*)d_in[17];
    float* out = (float*)d_out;

    void* p;
    cudaGetSymbolAddress(&p, g_h);    float* hB    = (float*)p;
    cudaGetSymbolAddress(&p, g_q);    float* qB    = (float*)p;
    cudaGetSymbolAddress(&p, g_k);    float* kB    = (float*)p;
    cudaGetSymbolAddress(&p, g_v);    float* vB    = (float*)p;
    cudaGetSymbolAddress(&p, g_attn); float* aB    = (float*)p;
    cudaGetSymbolAddress(&p, g_x1);   float* x1B   = (float*)p;
    cudaGetSymbolAddress(&p, g_h2);   float* h2B   = (float*)p;
    cudaGetSymbolAddress(&p, g_hmid); float* hmidB = (float*)p;
    cudaGetSymbolAddress(&p, g_y);    float* yB    = (float*)p;
    cudaGetSymbolAddress(&p, g_atok); int*   atokB = (int*)p;
    cudaGetSymbolAddress(&p, g_cnt);  int*   cntB  = (int*)p;
    cudaGetSymbolAddress(&p, g_off);  int*   offB  = (int*)p;

    // 1) RMSNorm1
    rmsnorm_kernel<<<S, 256>>>(x, n1w, hB);

    // 2) QKV projections
    gemm_kernel<0,false,false><<<dim3(8,16,1), 256>>>(hB, wq, bq, nullptr, qB, S, 1024, 1024, nullptr, nullptr, nullptr);
    gemm_kernel<0,false,false><<<dim3(2,16,1), 256>>>(hB, wk, bk, nullptr, kB, S,  256, 1024, nullptr, nullptr, nullptr);
    gemm_kernel<0,false,false><<<dim3(2,16,1), 256>>>(hB, wv, bv, nullptr, vB, S,  256, 1024, nullptr, nullptr, nullptr);

    // 3) sliding-window attention with sink
    attn_kernel<<<dim3(S/8, NH), 256>>>(sink);

    // 4) O-proj + residual
    gemm_kernel<1,false,false><<<dim3(8,16,1), 256>>>(aB, wo, bo, x, x1B, S, 1024, 1024, nullptr, nullptr, nullptr);

    // 5) RMSNorm2
    rmsnorm_kernel<<<S, 256>>>(x1B, n2w, h2B);

    // 6) router + grouping
    zero_kernel<<<1, 32>>>();
    router_kernel<<<S/8, 256>>>(rw, rb);
    offsets_kernel<<<1, 32>>>();
    place_kernel<<<8, 256>>>();
    colsum_kernel<<<NE, 256>>>();

    // 7) grouped MoE GEMMs (top-2 only)
    gemm_kernel<2,true, true><<<dim3(4,16,NE), 256>>>(h2B,   w1, b1, nullptr, hmidB, S,  512, 1024, atokB, cntB, offB);
    gemm_kernel<0,false,true><<<dim3(8,16,NE), 256>>>(hmidB, w2, b2, nullptr, yB,    S, 1024,  512, nullptr, cntB, offB);

    // 8) combine + residual, aux loss
    combine_kernel<<<S, 256>>>(out);
    aux_kernel<<<1, 32>>>(out, out_size);
}

// round 5
// speedup vs baseline: 1.6844x; 1.6821x over previous
#include <cuda_runtime.h>
#include <math.h>
#include <stdint.h>

#define S 2048
#define D 1024
#define NH 8
#define NKV 2
#define HD 128
#define WS 64
#define NE 16
#define HDIM 512
#define NA (S*2)

// ---------------- scratch (static device globals; no allocation) ------------
__device__ float g_h[S*D];
__device__ float g_q[S*D];
__device__ float g_k[S*NKV*HD];
__device__ float g_v[S*NKV*HD];
__device__ float g_attn[S*D];
__device__ float g_x1[S*D];
__device__ float g_h2[S*D];
__device__ float g_probs[S*NE];
__device__ float g_topw[S*2];
__device__ int   g_topi[S*2];
__device__ int   g_cnt[NE];
__device__ int   g_off[NE];
__device__ int   g_cur[NE];
__device__ int   g_atok[NA];
__device__ float g_aw[NA];
__device__ int   g_tslot[S*2];
__device__ float g_hmid[NA*HDIM];
__device__ float g_y[NA*D];
__device__ float g_colsum[NE];

// ---------------- RMSNorm: one block per row, 256 threads x float4 ----------
__global__ void rmsnorm_kernel(const float* __restrict__ x,
                               const float* __restrict__ w,
                               float* __restrict__ o) {
    int row = blockIdx.x;
    int tid = threadIdx.x;
    const float4* x4 = (const float4*)(x + (size_t)row * D);
    float4 v = x4[tid];
    float ss = v.x*v.x + v.y*v.y + v.z*v.z + v.w*v.w;
    __shared__ float red[8];
    #pragma unroll
    for (int s = 16; s; s >>= 1) ss += __shfl_xor_sync(0xffffffffu, ss, s);
    if ((tid & 31) == 0) red[tid >> 5] = ss;
    __syncthreads();
    if (tid < 32) {
        float t = (tid < 8) ? red[tid] : 0.f;
        #pragma unroll
        for (int s = 4; s; s >>= 1) t += __shfl_xor_sync(0xffffffffu, t, s);
        if (tid == 0) red[0] = t;
    }
    __syncthreads();
    float r = rsqrtf(red[0] * (1.0f / (float)D) + 1e-6f);
    const float4* w4 = (const float4*)w;
    float4 wv = w4[tid];
    float4 out;
    out.x = v.x * r * wv.x; out.y = v.y * r * wv.y;
    out.z = v.z * r * wv.z; out.w = v.w * r * wv.w;
    ((float4*)(o + (size_t)row * D))[tid] = out;
}

// ================== TF32 tensor-core GEMM ====================================
// C = A@B + bias [+resid][silu].  A row-major [M,K], B row-major [K,N].
// CTA tile 128x128x16, 8 warps (2x4), warp tile 64x32 via mma.m16n8k8.tf32.
// XSPLIT=1 -> 3xTF32 (hi/lo decomposition, ~fp32 accuracy).
#define BM 128
#define BN 128
#define BKT 16
#define ASTR 20     // conflict-free frag reads: (g*20+tg) distinct mod 32
#define BSTR 136    // conflict-free frag reads: (tg*8+g) distinct mod 32

// flat shared-memory indexing
#define AS_IX(s,r,c) ((s)*(BM*ASTR) + (r)*ASTR + (c))
#define BS_IX(s,r,c) ((s)*(BKT*BSTR) + (r)*BSTR + (c))

static __device__ __forceinline__ uint32_t f2tf(float x) {
    uint32_t r; asm("cvt.rna.tf32.f32 %0, %1;" : "=r"(r) : "f"(x)); return r;
}

static __device__ __forceinline__ void mma8(float* d, const uint32_t* a, const uint32_t* b) {
    asm volatile("mma.sync.aligned.m16n8k8.row.col.f32.tf32.tf32.f32 "
        "{%0,%1,%2,%3}, {%4,%5,%6,%7}, {%8,%9}, {%0,%1,%2,%3};\n"
        : "+f"(d[0]), "+f"(d[1]), "+f"(d[2]), "+f"(d[3])
        : "r"(a[0]), "r"(a[1]), "r"(a[2]), "r"(a[3]), "r"(b[0]), "r"(b[1]));
}

template<int XSPLIT, int XEPI, int XGATHER>
static __device__ __forceinline__ void gemm_core(
    uint32_t* Asm, uint32_t* Bsm,
    const float* __restrict__ A, const float* __restrict__ B,
    const float* __restrict__ bias, const float* __restrict__ resid,
    float* __restrict__ C, int M, int Nld, int K, int m0, int n0,
    const int* __restrict__ rowidx)
{
    int tid = threadIdx.x;
    int arow0 = tid >> 2, arow1 = arow0 + 64;
    int ac = (tid & 3) * 4;
    int r0 = m0 + arow0, r1 = m0 + arow1;
    bool v0 = r0 < M, v1 = r1 < M;
    int gr0 = v0 ? (XGATHER ? rowidx[r0] : r0) : 0;
    int gr1 = v1 ? (XGATHER ? rowidx[r1] : r1) : 0;
    const float* Ar0 = A + (size_t)gr0 * K;
    const float* Ar1 = A + (size_t)gr1 * K;
    int brow = tid >> 5;
    int bc = (tid & 31) * 4;
    const float* Bp0 = B + (size_t)brow * Nld + n0 + bc;
    const float* Bp1 = Bp0 + (size_t)8 * Nld;

    int lane = tid & 31, g = lane >> 2, tg = lane & 3;
    int wm = (tid >> 7) * 64;
    int wn = ((tid >> 5) & 3) * 32;

    float acc[4][4][4];
    #pragma unroll
    for (int i = 0; i < 4; i++) {
        #pragma unroll
        for (int j = 0; j < 4; j++) {
            #pragma unroll
            for (int c = 0; c < 4; c++) acc[i][j][c] = 0.f;
        }
    }

    float4 ra0, ra1, rb0, rb1;
    ra0 = v0 ? *(const float4*)(Ar0 + ac) : make_float4(0.f,0.f,0.f,0.f);
    ra1 = v1 ? *(const float4*)(Ar1 + ac) : make_float4(0.f,0.f,0.f,0.f);
    rb0 = *(const float4*)(Bp0);
    rb1 = *(const float4*)(Bp1);

    for (int k0 = 0; k0 < K; k0 += BKT) {
        __syncthreads();
        {
            float av[8] = {ra0.x, ra0.y, ra0.z, ra0.w, ra1.x, ra1.y, ra1.z, ra1.w};
            #pragma unroll
            for (int j = 0; j < 8; j++) {
                int row = (j < 4) ? arow0 : arow1;
                int col = ac + (j & 3);
                uint32_t hi = f2tf(av[j]);
                Asm[AS_IX(0, row, col)] = hi;
                if (XSPLIT) Asm[AS_IX(1, row, col)] = f2tf(av[j] - __uint_as_float(hi));
            }
            float bvv[8] = {rb0.x, rb0.y, rb0.z, rb0.w, rb1.x, rb1.y, rb1.z, rb1.w};
            #pragma unroll
            for (int j = 0; j < 8; j++) {
                int row = (j < 4) ? brow : (brow + 8);
                int col = bc + (j & 3);
                uint32_t hi = f2tf(bvv[j]);
                Bsm[BS_IX(0, row, col)] = hi;
                if (XSPLIT) Bsm[BS_IX(1, row, col)] = f2tf(bvv[j] - __uint_as_float(hi));
            }
        }
        __syncthreads();
        int kn = k0 + BKT;
        if (kn < K) {
            ra0 = v0 ? *(const float4*)(Ar0 + kn + ac) : make_float4(0.f,0.f,0.f,0.f);
            ra1 = v1 ? *(const float4*)(Ar1 + kn + ac) : make_float4(0.f,0.f,0.f,0.f);
            rb0 = *(const float4*)(Bp0 + (size_t)kn * Nld);
            rb1 = *(const float4*)(Bp1 + (size_t)kn * Nld);
        }
        #pragma unroll
        for (int ks = 0; ks < BKT; ks += 8) {
            uint32_t af[2][4][4], bf[2][4][2];
            #pragma unroll
            for (int i = 0; i < 4; i++) {
                int mb = wm + i*16 + g;
                af[0][i][0] = Asm[AS_IX(0, mb,   ks+tg)];
                af[0][i][1] = Asm[AS_IX(0, mb+8, ks+tg)];
                af[0][i][2] = Asm[AS_IX(0, mb,   ks+tg+4)];
                af[0][i][3] = Asm[AS_IX(0, mb+8, ks+tg+4)];
                if (XSPLIT) {
                    af[1][i][0] = Asm[AS_IX(1, mb,   ks+tg)];
                    af[1][i][1] = Asm[AS_IX(1, mb+8, ks+tg)];
                    af[1][i][2] = Asm[AS_IX(1, mb,   ks+tg+4)];
                    af[1][i][3] = Asm[AS_IX(1, mb+8, ks+tg+4)];
                }
            }
            #pragma unroll
            for (int j = 0; j < 4; j++) {
                int nb = wn + j*8 + g;
                bf[0][j][0] = Bsm[BS_IX(0, ks+tg,   nb)];
                bf[0][j][1] = Bsm[BS_IX(0, ks+tg+4, nb)];
                if (XSPLIT) {
                    bf[1][j][0] = Bsm[BS_IX(1, ks+tg,   nb)];
                    bf[1][j][1] = Bsm[BS_IX(1, ks+tg+4, nb)];
                }
            }
            #pragma unroll
            for (int i = 0; i < 4; i++) {
                #pragma unroll
                for (int j = 0; j < 4; j++) mma8(acc[i][j], af[0][i], bf[0][j]);
            }
            if (XSPLIT) {
                #pragma unroll
                for (int i = 0; i < 4; i++) {
                    #pragma unroll
                    for (int j = 0; j < 4; j++) mma8(acc[i][j], af[0][i], bf[1][j]);
                }
                #pragma unroll
                for (int i = 0; i < 4; i++) {
                    #pragma unroll
                    for (int j = 0; j < 4; j++) mma8(acc[i][j], af[1][i], bf[0][j]);
                }
            }
        }
    }

    // epilogue: mma C frag mapping: c0,c1 -> (g, 2tg,2tg+1); c2,c3 -> (g+8, ...)
    #pragma unroll
    for (int i = 0; i < 4; i++) {
        int rr0 = m0 + wm + i*16 + g;
        int rr1 = rr0 + 8;
        #pragma unroll
        for (int j = 0; j < 4; j++) {
            int c = n0 + wn + j*8 + tg*2;
            float b0v = bias[c], b1v = bias[c+1];
            if (rr0 < M) {
                float t0 = acc[i][j][0] + b0v;
                float t1 = acc[i][j][1] + b1v;
                if (XEPI == 1) {
                    t0 += resid[(size_t)rr0*Nld + c];
                    t1 += resid[(size_t)rr0*Nld + c + 1];
                }
                if (XEPI == 2) {
                    t0 = t0 / (1.f + expf(-t0));
                    t1 = t1 / (1.f + expf(-t1));
                }
                float2 o; o.x = t0; o.y = t1;
                *(float2*)&C[(size_t)rr0*Nld + c] = o;
            }
            if (rr1 < M) {
                float t0 = acc[i][j][2] + b0v;
                float t1 = acc[i][j][3] + b1v;
                if (XEPI == 1) {
                    t0 += resid[(size_t)rr1*Nld + c];
                    t1 += resid[(size_t)rr1*Nld + c + 1];
                }
                if (XEPI == 2) {
                    t0 = t0 / (1.f + expf(-t0));
                    t1 = t1 / (1.f + expf(-t1));
                }
                float2 o; o.x = t0; o.y = t1;
                *(float2*)&C[(size_t)rr1*Nld + c] = o;
            }
        }
    }
}

// ---- fused QKV (3xTF32): grid (12, 16) -------------------------------------
__global__ void __launch_bounds__(256) qkv_kernel(
    const float* __restrict__ h,
    const float* __restrict__ wq, const float* __restrict__ bq,
    const float* __restrict__ wk, const float* __restrict__ bk,
    const float* __restrict__ wv, const float* __restrict__ bv)
{
    __shared__ uint32_t Asm[2*BM*ASTR];
    __shared__ uint32_t Bsm[2*BKT*BSTR];
    int x = blockIdx.x, m0 = blockIdx.y * BM;
    if (x < 8)
        gemm_core<1,0,0>(Asm, Bsm, h, wq, bq, nullptr, g_q, S, 1024, 1024, m0, x*128, nullptr);
    else if (x < 10)
        gemm_core<1,0,0>(Asm, Bsm, h, wk, bk, nullptr, g_k, S, 256, 1024, m0, (x-8)*128, nullptr);
    else
        gemm_core<1,0,0>(Asm, Bsm, h, wv, bv, nullptr, g_v, S, 256, 1024, m0, (x-10)*128, nullptr);
}

// ---- O-proj + residual (3xTF32): grid (8, 16) -------------------------------
__global__ void __launch_bounds__(256) oproj_kernel(
    const float* __restrict__ wo, const float* __restrict__ bo,
    const float* __restrict__ x)
{
    __shared__ uint32_t Asm[2*BM*ASTR];
    __shared__ uint32_t Bsm[2*BKT*BSTR];
    gemm_core<1,1,0>(Asm, Bsm, g_attn, wo, bo, x, g_x1, S, 1024, 1024,
                     blockIdx.y*BM, blockIdx.x*BN, nullptr);
}

// ---- MoE expert GEMMs (1xTF32, grouped) -------------------------------------
__global__ void __launch_bounds__(256) moe1_kernel(
    const float* __restrict__ h2, const float* __restrict__ w1,
    const float* __restrict__ b1)
{
    int e = blockIdx.z;
    int M = g_cnt[e];
    int m0 = blockIdx.y * BM;
    if (m0 >= M) return;
    int o = g_off[e];
    __shared__ uint32_t Asm[BM*ASTR];
    __shared__ uint32_t Bsm[BKT*BSTR];
    gemm_core<0,2,1>(Asm, Bsm, h2, w1 + (size_t)e*1024*512, b1 + (size_t)e*512,
                     nullptr, g_hmid + (size_t)o*512, M, 512, 1024,
                     m0, blockIdx.x*BN, g_atok + o);
}

__global__ void __launch_bounds__(256) moe2_kernel(
    const float* __restrict__ w2, const float* __restrict__ b2)
{
    int e = blockIdx.z;
    int M = g_cnt[e];
    int m0 = blockIdx.y * BM;
    if (m0 >= M) return;
    int o = g_off[e];
    __shared__ uint32_t Asm[BM*ASTR];
    __shared__ uint32_t Bsm[BKT*BSTR];
    gemm_core<0,0,0>(Asm, Bsm, g_hmid + (size_t)o*512, w2 + (size_t)e*512*1024,
                     b2 + (size_t)e*1024, nullptr, g_y + (size_t)o*1024,
                     M, 1024, 512, m0, blockIdx.x*BN, nullptr);
}

// ---------------- sliding-window attention, 1 warp = 1 query row ------------
__global__ void attn_kernel(const float* __restrict__ sinkp) {
    int warp = threadIdx.x >> 5, lane = threadIdx.x & 31;
    int i = blockIdx.x * 8 + warp;
    int h = blockIdx.y;
    int kvh = h >> 2;  // NH/NKV = 4
    const float scale = 0.08838834764831845f;  // 1/sqrt(128)

    float qr[4];
    const float* qp = g_q + (size_t)i * D + h * HD;
    #pragma unroll
    for (int c = 0; c < 4; c++) qr[c] = qp[lane + 32 * c];

    int jstart = (i >= (WS - 1)) ? (i - (WS - 1)) : 0;
    int cnt = i - jstart + 1;

    float s0 = -1e30f, s1 = -1e30f;
    for (int jj = 0; jj < cnt; ++jj) {
        const float* kp = g_k + (size_t)(jstart + jj) * (NKV * HD) + kvh * HD;
        float p = qr[0]*kp[lane] + qr[1]*kp[lane+32] + qr[2]*kp[lane+64] + qr[3]*kp[lane+96];
        #pragma unroll
        for (int s = 16; s; s >>= 1) p += __shfl_xor_sync(0xffffffffu, p, s);
        p *= scale;
        if ((jj & 31) == lane) { if (jj < 32) s0 = p; else s1 = p; }
    }
    float sink = *sinkp;
    float m = fmaxf(s0, s1);
    #pragma unroll
    for (int s = 16; s; s >>= 1) m = fmaxf(m, __shfl_xor_sync(0xffffffffu, m, s));
    m = fmaxf(m, sink);
    float e0 = expf(s0 - m), e1 = expf(s1 - m);
    float dsum = e0 + e1;
    #pragma unroll
    for (int s = 16; s; s >>= 1) dsum += __shfl_xor_sync(0xffffffffu, dsum, s);
    dsum += expf(sink - m);
    float inv = 1.f / dsum;

    float o0 = 0.f, o1 = 0.f, o2 = 0.f, o3 = 0.f;
    for (int jj = 0; jj < cnt; ++jj) {
        float pv = (jj < 32) ? e0 : e1;
        float p = __shfl_sync(0xffffffffu, pv, jj & 31);
        const float* vp = g_v + (size_t)(jstart + jj) * (NKV * HD) + kvh * HD;
        o0 += p * vp[lane];      o1 += p * vp[lane + 32];
        o2 += p * vp[lane + 64]; o3 += p * vp[lane + 96];
    }
    float* op = g_attn + (size_t)i * D + h * HD;
    op[lane]      = o0 * inv; op[lane + 32] = o1 * inv;
    op[lane + 64] = o2 * inv; op[lane + 96] = o3 * inv;
}

// ---------------- router: 1 warp = 1 token ----------------------------------
__global__ void router_kernel(const float* __restrict__ rw, const float* __restrict__ rb) {
    int warp = threadIdx.x >> 5, lane = threadIdx.x & 31;
    int t = blockIdx.x * 8 + warp;
    float acc[NE];
    #pragma unroll
    for (int e = 0; e < NE; e++) acc[e] = 0.f;
    const float* xr = g_h2 + (size_t)t * D;
    for (int d = lane; d < D; d += 32) {
        float xv = xr[d];
        const float* rr = rw + d * NE;
        #pragma unroll
        for (int e = 0; e < NE; e++) acc[e] += xv * rr[e];
    }
    #pragma unroll
    for (int e = 0; e < NE; e++) {
        float a = acc[e];
        #pragma unroll
        for (int s = 16; s; s >>= 1) a += __shfl_xor_sync(0xffffffffu, a, s);
        acc[e] = a;
    }
    if (lane == 0) {
        float logit[NE]; float m = -1e30f;
        #pragma unroll
        for (int e = 0; e < NE; e++) { logit[e] = (acc[e] + rb[e]) * 10.f; m = fmaxf(m, logit[e]); }
        float pe[NE]; float ssum = 0.f;
        #pragma unroll
        for (int e = 0; e < NE; e++) { pe[e] = expf(logit[e] - m); ssum += pe[e]; }
        float invs = 1.f / ssum;
        #pragma unroll
        for (int e = 0; e < NE; e++) g_probs[t * NE + e] = pe[e] * invs;
        int i0 = 0; float v0 = logit[0];
        #pragma unroll
        for (int e = 1; e < NE; e++) if (logit[e] > v0) { v0 = logit[e]; i0 = e; }
        int i1 = -1; float v1 = -1e30f;
        #pragma unroll
        for (int e = 0; e < NE; e++) if (e != i0 && logit[e] > v1) { v1 = logit[e]; i1 = e; }
        float ex = expf(v1 - v0);
        float w0 = 1.f / (1.f + ex);
        g_topi[t*2] = i0; g_topi[t*2+1] = i1;
        g_topw[t*2] = w0; g_topw[t*2+1] = 1.f - w0;
        atomicAdd(&g_cnt[i0], 1); atomicAdd(&g_cnt[i1], 1);
    }
}

__global__ void zero_kernel() {
    int t = threadIdx.x;
    if (t < NE) { g_cnt[t] = 0; g_cur[t] = 0; }
}

__global__ void offsets_kernel() {
    if (threadIdx.x == 0) {
        int s = 0;
        for (int e = 0; e < NE; e++) { g_off[e] = s; s += g_cnt[e]; }
    }
}

__global__ void place_kernel() {
    int t = blockIdx.x * blockDim.x + threadIdx.x;
    if (t >= S) return;
    #pragma unroll
    for (int k2 = 0; k2 < 2; k2++) {
        int e = g_topi[t*2 + k2];
        int slot = g_off[e] + atomicAdd(&g_cur[e], 1);
        g_atok[slot] = t;
        g_aw[slot] = g_topw[t*2 + k2];
        g_tslot[t*2 + k2] = slot;
    }
}

__global__ void colsum_kernel() {
    int e = blockIdx.x; int tid = threadIdx.x;
    float s = 0.f;
    for (int t = tid; t < S; t += 256) s += g_probs[t * NE + e];
    __shared__ float red[256];
    red[tid] = s; __syncthreads();
    for (int st = 128; st; st >>= 1) { if (tid < st) red[tid] += red[tid + st]; __syncthreads(); }
    if (tid == 0) g_colsum[e] = red[0];
}

__global__ void combine_kernel(float* __restrict__ out) {
    int t = blockIdx.x; int c = threadIdx.x;
    int s0 = g_tslot[t*2], s1 = g_tslot[t*2+1];
    float w0 = g_aw[s0], w1 = g_aw[s1];
    const float4* x14 = (const float4*)(g_x1 + (size_t)t * D);
    const float4* y0  = (const float4*)(g_y + (size_t)s0 * D);
    const float4* y1  = (const float4*)(g_y + (size_t)s1 * D);
    float4 a = x14[c], b = y0[c], d2 = y1[c];
    float4 o;
    o.x = a.x + w0*b.x + w1*d2.x; o.y = a.y + w0*b.y + w1*d2.y;
    o.z = a.z + w0*b.z + w1*d2.z; o.w = a.w + w0*b.w + w1*d2.w;
    ((float4*)out)[(size_t)t * (D/4) + c] = o;
}

__global__ void aux_kernel(float* __restrict__ out, int out_size) {
    int tid = threadIdx.x;
    float v = (tid < NE) ? g_colsum[tid] * g_colsum[tid] : 0.f;
    #pragma unroll
    for (int s = 16; s; s >>= 1) v += __shfl_xor_sync(0xffffffffu, v, s);
    if (tid == 0) {
        float aux = v * (1.0f / (float)NE) * 1e-5f;
        for (int idx = S * D; idx < out_size; ++idx) out[idx] = aux;
    }
}

// ---------------- launch -----------------------------------------------------
extern "C" void kernel_launch(void* const* d_in, const int* in_sizes, int n_in,
                              void* d_out, int out_size) {
    const float* x    = (const float*)d_in[0];
    const float* n1w  = (const float*)d_in[1];
    const float* wq   = (const float*)d_in[2];
    const float* bq   = (const float*)d_in[3];
    const float* wk   = (const float*)d_in[4];
    const float* bk   = (const float*)d_in[5];
    const float* wv   = (const float*)d_in[6];
    const float* bv   = (const float*)d_in[7];
    const float* wo   = (const float*)d_in[8];
    const float* bo   = (const float*)d_in[9];
    const float* sink = (const float*)d_in[10];
    const float* n2w  = (const float*)d_in[11];
    const float* rw   = (const float*)d_in[12];
    const float* rb   = (const float*)d_in[13];
    const float* w1   = (const float*)d_in[14];
    const float* b1   = (const float*)d_in[15];
    const float* w2   = (const float*)d_in[16];
    const float* b2   = (const float*)d_in[17];
    float* out = (float*)d_out;

    void* p;
    cudaGetSymbolAddress(&p, g_h);    float* hB    = (float*)p;
    cudaGetSymbolAddress(&p, g_x1);   float* x1B   = (float*)p;
    cudaGetSymbolAddress(&p, g_h2);   float* h2B   = (float*)p;

    // 1) RMSNorm1
    rmsnorm_kernel<<<S, 256>>>(x, n1w, hB);

    // 2) fused QKV projections (3xTF32 tensor cores)
    qkv_kernel<<<dim3(12, 16), 256>>>(hB, wq, bq, wk, bk, wv, bv);

    // 3) sliding-window attention with sink
    attn_kernel<<<dim3(S/8, NH), 256>>>(sink);

    // 4) O-proj + residual (3xTF32)
    oproj_kernel<<<dim3(8, 16), 256>>>(wo, bo, x);

    // 5) RMSNorm2
    rmsnorm_kernel<<<S, 256>>>(x1B, n2w, h2B);

    // 6) router + grouping
    zero_kernel<<<1, 32>>>();
    router_kernel<<<S/8, 256>>>(rw, rb);
    offsets_kernel<<<1, 32>>>();
    place_kernel<<<8, 256>>>();
    colsum_kernel<<<NE, 256>>>();

    // 7) grouped MoE GEMMs (top-2 only, 1xTF32)
    moe1_kernel<<<dim3(4, 16, NE), 256>>>(h2B, w1, b1);
    moe2_kernel<<<dim3(8, 16, NE), 256>>>(w2, b2);

    // 8) combine + residual, aux loss
    combine_kernel<<<S, 256>>>(out);
    aux_kernel<<<1, 32>>>(out, out_size);
}

// round 6
// speedup vs baseline: 1.9914x; 1.1823x over previous
#include <cuda_runtime.h>
#include <math.h>
#include <stdint.h>

#define S 2048
#define D 1024
#define NH 8
#define NKV 2
#define HD 128
#define WS 64
#define NE 16
#define HDIM 512
#define NA (S*2)

// ---------------- scratch (static device globals; no allocation) ------------
__device__ float g_h[S*D];
__device__ float g_q[S*D];
__device__ float g_k[S*NKV*HD];
__device__ float g_v[S*NKV*HD];
__device__ float g_attn[S*D];
__device__ float g_x1[S*D];
__device__ float g_h2[S*D];
__device__ float g_probs[S*NE];
__device__ float g_topw[S*2];
__device__ int   g_topi[S*2];
__device__ int   g_cnt[NE];
__device__ int   g_off[NE];
__device__ int   g_cur[NE];
__device__ int   g_atok[NA];
__device__ float g_aw[NA];
__device__ int   g_tslot[S*2];
__device__ float g_hmid[NA*HDIM];
__device__ float g_y[NA*D];
__device__ float g_colsum[NE];

// ---------------- RMSNorm: one block per row, 256 threads x float4 ----------
__global__ void rmsnorm_kernel(const float* __restrict__ x,
                               const float* __restrict__ w,
                               float* __restrict__ o) {
    int row = blockIdx.x;
    int tid = threadIdx.x;
    const float4* x4 = (const float4*)(x + (size_t)row * D);
    float4 v = x4[tid];
    float ss = v.x*v.x + v.y*v.y + v.z*v.z + v.w*v.w;
    __shared__ float red[8];
    #pragma unroll
    for (int s = 16; s; s >>= 1) ss += __shfl_xor_sync(0xffffffffu, ss, s);
    if ((tid & 31) == 0) red[tid >> 5] = ss;
    __syncthreads();
    if (tid < 32) {
        float t = (tid < 8) ? red[tid] : 0.f;
        #pragma unroll
        for (int s = 4; s; s >>= 1) t += __shfl_xor_sync(0xffffffffu, t, s);
        if (tid == 0) red[0] = t;
    }
    __syncthreads();
    float r = rsqrtf(red[0] * (1.0f / (float)D) + 1e-6f);
    const float4* w4 = (const float4*)w;
    float4 wv = w4[tid];
    float4 out;
    out.x = v.x * r * wv.x; out.y = v.y * r * wv.y;
    out.z = v.z * r * wv.z; out.w = v.w * r * wv.w;
    ((float4*)(o + (size_t)row * D))[tid] = out;
}

// ================== TF32 tensor-core GEMM ====================================
// C = A@B + bias [+resid][silu].  A row-major [M,K], B row-major [K,N].
// CTA tile 64x128x16, 8 warps (2x4), warp tile 32x32 via mma.m16n8k8.tf32.
// Double-buffered smem, 1 syncthreads per k-iter.
// XSPLIT=1 -> 3xTF32 (hi/lo decomposition, ~fp32 accuracy).
#define BM 64
#define BN 128
#define BKT 16
#define ASTR 20     // conflict-free frag reads: (g*20+tg) distinct mod 32
#define BSTR 136    // conflict-free frag reads: (tg*8+g) distinct mod 32
#define APLANE (BM*ASTR)   // 1280 words
#define BPLANE (BKT*BSTR)  // 2176 words

static __device__ __forceinline__ uint32_t f2tf(float x) {
    uint32_t r; asm("cvt.rna.tf32.f32 %0, %1;" : "=r"(r) : "f"(x)); return r;
}

static __device__ __forceinline__ void mma8(float* d, const uint32_t* a, const uint32_t* b) {
    asm volatile("mma.sync.aligned.m16n8k8.row.col.f32.tf32.tf32.f32 "
        "{%0,%1,%2,%3}, {%4,%5,%6,%7}, {%8,%9}, {%0,%1,%2,%3};\n"
        : "+f"(d[0]), "+f"(d[1]), "+f"(d[2]), "+f"(d[3])
        : "r"(a[0]), "r"(a[1]), "r"(a[2]), "r"(a[3]), "r"(b[0]), "r"(b[1]));
}

// store one k-tile (registers -> smem stage), converting to tf32 (+lo plane)
#define STORE_TILE(stg) do { \
    uint32_t* Ab = Asm + (stg) * ASTAGE; \
    uint32_t* Bb = Bsm + (stg) * BSTAGE; \
    float av[4] = {ra.x, ra.y, ra.z, ra.w}; \
    _Pragma("unroll") \
    for (int j = 0; j < 4; j++) { \
        uint32_t hi = f2tf(av[j]); \
        Ab[arow*ASTR + ac + j] = hi; \
        if (XSPLIT) Ab[APLANE + arow*ASTR + ac + j] = f2tf(av[j] - __uint_as_float(hi)); \
    } \
    float bvv[8] = {rb0v.x, rb0v.y, rb0v.z, rb0v.w, rb1v.x, rb1v.y, rb1v.z, rb1v.w}; \
    _Pragma("unroll") \
    for (int j = 0; j < 8; j++) { \
        int row = (j < 4) ? brow : (brow + 8); \
        int col = bc + (j & 3); \
        uint32_t hi = f2tf(bvv[j]); \
        Bb[row*BSTR + col] = hi; \
        if (XSPLIT) Bb[BPLANE + row*BSTR + col] = f2tf(bvv[j] - __uint_as_float(hi)); \
    } \
} while (0)

template<int XSPLIT, int XEPI, int XGATHER>
static __device__ __forceinline__ void gemm_core(
    uint32_t* Asm, uint32_t* Bsm,
    const float* __restrict__ A, const float* __restrict__ B,
    const float* __restrict__ bias, const float* __restrict__ resid,
    float* __restrict__ C, int M, int Nld, int K, int m0, int n0,
    const int* __restrict__ rowidx)
{
    const int ASTAGE = (XSPLIT ? 2 : 1) * APLANE;
    const int BSTAGE = (XSPLIT ? 2 : 1) * BPLANE;

    int tid = threadIdx.x;
    int arow = tid >> 2;
    int ac = (tid & 3) * 4;
    int r0 = m0 + arow;
    bool v0 = r0 < M;
    int gr0 = v0 ? (XGATHER ? rowidx[r0] : r0) : 0;
    const float* Ar0 = A + (size_t)gr0 * K;
    int brow = tid >> 5;
    int bc = (tid & 31) * 4;
    const float* Bp0 = B + (size_t)brow * Nld + n0 + bc;
    const float* Bp1 = Bp0 + (size_t)8 * Nld;

    int lane = tid & 31, g = lane >> 2, tg = lane & 3;
    int wm = (tid >> 7) * 32;
    int wn = ((tid >> 5) & 3) * 32;

    float acc[2][4][4];
    #pragma unroll
    for (int i = 0; i < 2; i++) {
        #pragma unroll
        for (int j = 0; j < 4; j++) {
            #pragma unroll
            for (int c = 0; c < 4; c++) acc[i][j][c] = 0.f;
        }
    }

    float4 ra  = v0 ? *(const float4*)(Ar0 + ac) : make_float4(0.f,0.f,0.f,0.f);
    float4 rb0v = *(const float4*)(Bp0);
    float4 rb1v = *(const float4*)(Bp1);
    STORE_TILE(0);
    __syncthreads();
    int cur = 0;

    for (int k0 = 0; k0 < K; k0 += BKT) {
        int kn = k0 + BKT;
        bool more = kn < K;
        if (more) {
            ra  = v0 ? *(const float4*)(Ar0 + kn + ac) : make_float4(0.f,0.f,0.f,0.f);
            rb0v = *(const float4*)(Bp0 + (size_t)kn * Nld);
            rb1v = *(const float4*)(Bp1 + (size_t)kn * Nld);
        }
        const uint32_t* Ab = Asm + cur * ASTAGE;
        const uint32_t* Bb = Bsm + cur * BSTAGE;
        #pragma unroll
        for (int ks = 0; ks < BKT; ks += 8) {
            uint32_t af[2][2][4], bf[2][4][2];
            #pragma unroll
            for (int i = 0; i < 2; i++) {
                int mb = wm + i*16 + g;
                af[0][i][0] = Ab[mb*ASTR + ks+tg];
                af[0][i][1] = Ab[(mb+8)*ASTR + ks+tg];
                af[0][i][2] = Ab[mb*ASTR + ks+tg+4];
                af[0][i][3] = Ab[(mb+8)*ASTR + ks+tg+4];
                if (XSPLIT) {
                    af[1][i][0] = Ab[APLANE + mb*ASTR + ks+tg];
                    af[1][i][1] = Ab[APLANE + (mb+8)*ASTR + ks+tg];
                    af[1][i][2] = Ab[APLANE + mb*ASTR + ks+tg+4];
                    af[1][i][3] = Ab[APLANE + (mb+8)*ASTR + ks+tg+4];
                }
            }
            #pragma unroll
            for (int j = 0; j < 4; j++) {
                int nb = wn + j*8 + g;
                bf[0][j][0] = Bb[(ks+tg)*BSTR + nb];
                bf[0][j][1] = Bb[(ks+tg+4)*BSTR + nb];
                if (XSPLIT) {
                    bf[1][j][0] = Bb[BPLANE + (ks+tg)*BSTR + nb];
                    bf[1][j][1] = Bb[BPLANE + (ks+tg+4)*BSTR + nb];
                }
            }
            #pragma unroll
            for (int i = 0; i < 2; i++) {
                #pragma unroll
                for (int j = 0; j < 4; j++) mma8(acc[i][j], af[0][i], bf[0][j]);
            }
            if (XSPLIT) {
                #pragma unroll
                for (int i = 0; i < 2; i++) {
                    #pragma unroll
                    for (int j = 0; j < 4; j++) mma8(acc[i][j], af[0][i], bf[1][j]);
                }
                #pragma unroll
                for (int i = 0; i < 2; i++) {
                    #pragma unroll
                    for (int j = 0; j < 4; j++) mma8(acc[i][j], af[1][i], bf[0][j]);
                }
            }
        }
        if (more) {
            STORE_TILE(cur ^ 1);
            __syncthreads();
            cur ^= 1;
        }
    }

    // epilogue: mma C frag mapping: c0,c1 -> (g, 2tg,2tg+1); c2,c3 -> (g+8, ...)
    #pragma unroll
    for (int i = 0; i < 2; i++) {
        int rr0 = m0 + wm + i*16 + g;
        int rr1 = rr0 + 8;
        #pragma unroll
        for (int j = 0; j < 4; j++) {
            int c = n0 + wn + j*8 + tg*2;
            float b0v = bias[c], b1v = bias[c+1];
            if (rr0 < M) {
                float t0 = acc[i][j][0] + b0v;
                float t1 = acc[i][j][1] + b1v;
                if (XEPI == 1) {
                    t0 += resid[(size_t)rr0*Nld + c];
                    t1 += resid[(size_t)rr0*Nld + c + 1];
                }
                if (XEPI == 2) {
                    t0 = t0 / (1.f + expf(-t0));
                    t1 = t1 / (1.f + expf(-t1));
                }
                float2 o; o.x = t0; o.y = t1;
                *(float2*)&C[(size_t)rr0*Nld + c] = o;
            }
            if (rr1 < M) {
                float t0 = acc[i][j][2] + b0v;
                float t1 = acc[i][j][3] + b1v;
                if (XEPI == 1) {
                    t0 += resid[(size_t)rr1*Nld + c];
                    t1 += resid[(size_t)rr1*Nld + c + 1];
                }
                if (XEPI == 2) {
                    t0 = t0 / (1.f + expf(-t0));
                    t1 = t1 / (1.f + expf(-t1));
                }
                float2 o; o.x = t0; o.y = t1;
                *(float2*)&C[(size_t)rr1*Nld + c] = o;
            }
        }
    }
}

// dynamic smem words for split kernels: 2 stages x (2 planes A + 2 planes B)
#define SPLIT_SMEM_BYTES ((2*(2*APLANE) + 2*(2*BPLANE)) * 4)

// ---- fused QKV (3xTF32): grid (12, 32) -------------------------------------
__global__ void __launch_bounds__(256, 2) qkv_kernel(
    const float* __restrict__ h,
    const float* __restrict__ wq, const float* __restrict__ bq,
    const float* __restrict__ wk, const float* __restrict__ bk,
    const float* __restrict__ wv, const float* __restrict__ bv)
{
    extern __shared__ uint32_t dynsmem[];
    uint32_t* Asm = dynsmem;
    uint32_t* Bsm = dynsmem + 2*(2*APLANE);
    int x = blockIdx.x, m0 = blockIdx.y * BM;
    if (x < 8)
        gemm_core<1,0,0>(Asm, Bsm, h, wq, bq, nullptr, g_q, S, 1024, 1024, m0, x*128, nullptr);
    else if (x < 10)
        gemm_core<1,0,0>(Asm, Bsm, h, wk, bk, nullptr, g_k, S, 256, 1024, m0, (x-8)*128, nullptr);
    else
        gemm_core<1,0,0>(Asm, Bsm, h, wv, bv, nullptr, g_v, S, 256, 1024, m0, (x-10)*128, nullptr);
}

// ---- O-proj + residual (3xTF32): grid (8, 32) -------------------------------
__global__ void __launch_bounds__(256, 2) oproj_kernel(
    const float* __restrict__ wo, const float* __restrict__ bo,
    const float* __restrict__ x)
{
    extern __shared__ uint32_t dynsmem[];
    uint32_t* Asm = dynsmem;
    uint32_t* Bsm = dynsmem + 2*(2*APLANE);
    gemm_core<1,1,0>(Asm, Bsm, g_attn, wo, bo, x, g_x1, S, 1024, 1024,
                     blockIdx.y*BM, blockIdx.x*BN, nullptr);
}

// ---- MoE expert GEMMs (1xTF32, grouped, static 2-stage smem) ----------------
__global__ void __launch_bounds__(256, 2) moe1_kernel(
    const float* __restrict__ h2, const float* __restrict__ w1,
    const float* __restrict__ b1)
{
    int e = blockIdx.z;
    int M = g_cnt[e];
    int m0 = blockIdx.y * BM;
    if (m0 >= M) return;
    int o = g_off[e];
    __shared__ uint32_t sA[2*APLANE];
    __shared__ uint32_t sB[2*BPLANE];
    gemm_core<0,2,1>(sA, sB, h2, w1 + (size_t)e*1024*512, b1 + (size_t)e*512,
                     nullptr, g_hmid + (size_t)o*512, M, 512, 1024,
                     m0, blockIdx.x*BN, g_atok + o);
}

__global__ void __launch_bounds__(256, 2) moe2_kernel(
    const float* __restrict__ w2, const float* __restrict__ b2)
{
    int e = blockIdx.z;
    int M = g_cnt[e];
    int m0 = blockIdx.y * BM;
    if (m0 >= M) return;
    int o = g_off[e];
    __shared__ uint32_t sA[2*APLANE];
    __shared__ uint32_t sB[2*BPLANE];
    gemm_core<0,0,0>(sA, sB, g_hmid + (size_t)o*512, w2 + (size_t)e*512*1024,
                     b2 + (size_t)e*1024, nullptr, g_y + (size_t)o*1024,
                     M, 1024, 512, m0, blockIdx.x*BN, nullptr);
}

// ---------------- sliding-window attention, 1 warp = 1 query row ------------
__global__ void attn_kernel(const float* __restrict__ sinkp) {
    int warp = threadIdx.x >> 5, lane = threadIdx.x & 31;
    int i = blockIdx.x * 8 + warp;
    int h = blockIdx.y;
    int kvh = h >> 2;  // NH/NKV = 4
    const float scale = 0.08838834764831845f;  // 1/sqrt(128)

    float qr[4];
    const float* qp = g_q + (size_t)i * D + h * HD;
    #pragma unroll
    for (int c = 0; c < 4; c++) qr[c] = qp[lane + 32 * c];

    int jstart = (i >= (WS - 1)) ? (i - (WS - 1)) : 0;
    int cnt = i - jstart + 1;

    float s0 = -1e30f, s1 = -1e30f;
    for (int jj = 0; jj < cnt; ++jj) {
        const float* kp = g_k + (size_t)(jstart + jj) * (NKV * HD) + kvh * HD;
        float p = qr[0]*kp[lane] + qr[1]*kp[lane+32] + qr[2]*kp[lane+64] + qr[3]*kp[lane+96];
        #pragma unroll
        for (int s = 16; s; s >>= 1) p += __shfl_xor_sync(0xffffffffu, p, s);
        p *= scale;
        if ((jj & 31) == lane) { if (jj < 32) s0 = p; else s1 = p; }
    }
    float sink = *sinkp;
    float m = fmaxf(s0, s1);
    #pragma unroll
    for (int s = 16; s; s >>= 1) m = fmaxf(m, __shfl_xor_sync(0xffffffffu, m, s));
    m = fmaxf(m, sink);
    float e0 = expf(s0 - m), e1 = expf(s1 - m);
    float dsum = e0 + e1;
    #pragma unroll
    for (int s = 16; s; s >>= 1) dsum += __shfl_xor_sync(0xffffffffu, dsum, s);
    dsum += expf(sink - m);
    float inv = 1.f / dsum;

    float o0 = 0.f, o1 = 0.f, o2 = 0.f, o3 = 0.f;
    for (int jj = 0; jj < cnt; ++jj) {
        float pv = (jj < 32) ? e0 : e1;
        float p = __shfl_sync(0xffffffffu, pv, jj & 31);
        const float* vp = g_v + (size_t)(jstart + jj) * (NKV * HD) + kvh * HD;
        o0 += p * vp[lane];      o1 += p * vp[lane + 32];
        o2 += p * vp[lane + 64]; o3 += p * vp[lane + 96];
    }
    float* op = g_attn + (size_t)i * D + h * HD;
    op[lane]      = o0 * inv; op[lane + 32] = o1 * inv;
    op[lane + 64] = o2 * inv; op[lane + 96] = o3 * inv;
}

// ---------------- router: 1 warp = 1 token ----------------------------------
__global__ void router_kernel(const float* __restrict__ rw, const float* __restrict__ rb) {
    int warp = threadIdx.x >> 5, lane = threadIdx.x & 31;
    int t = blockIdx.x * 8 + warp;
    float acc[NE];
    #pragma unroll
    for (int e = 0; e < NE; e++) acc[e] = 0.f;
    const float* xr = g_h2 + (size_t)t * D;
    for (int d = lane; d < D; d += 32) {
        float xv = xr[d];
        const float* rr = rw + d * NE;
        #pragma unroll
        for (int e = 0; e < NE; e++) acc[e] += xv * rr[e];
    }
    #pragma unroll
    for (int e = 0; e < NE; e++) {
        float a = acc[e];
        #pragma unroll
        for (int s = 16; s; s >>= 1) a += __shfl_xor_sync(0xffffffffu, a, s);
        acc[e] = a;
    }
    if (lane == 0) {
        float logit[NE]; float m = -1e30f;
        #pragma unroll
        for (int e = 0; e < NE; e++) { logit[e] = (acc[e] + rb[e]) * 10.f; m = fmaxf(m, logit[e]); }
        float pe[NE]; float ssum = 0.f;
        #pragma unroll
        for (int e = 0; e < NE; e++) { pe[e] = expf(logit[e] - m); ssum += pe[e]; }
        float invs = 1.f / ssum;
        #pragma unroll
        for (int e = 0; e < NE; e++) g_probs[t * NE + e] = pe[e] * invs;
        int i0 = 0; float v0 = logit[0];
        #pragma unroll
        for (int e = 1; e < NE; e++) if (logit[e] > v0) { v0 = logit[e]; i0 = e; }
        int i1 = -1; float v1 = -1e30f;
        #pragma unroll
        for (int e = 0; e < NE; e++) if (e != i0 && logit[e] > v1) { v1 = logit[e]; i1 = e; }
        float ex = expf(v1 - v0);
        float w0 = 1.f / (1.f + ex);
        g_topi[t*2] = i0; g_topi[t*2+1] = i1;
        g_topw[t*2] = w0; g_topw[t*2+1] = 1.f - w0;
        atomicAdd(&g_cnt[i0], 1); atomicAdd(&g_cnt[i1], 1);
    }
}

__global__ void zero_kernel() {
    int t = threadIdx.x;
    if (t < NE) { g_cnt[t] = 0; g_cur[t] = 0; }
}

__global__ void offsets_kernel() {
    if (threadIdx.x == 0) {
        int s = 0;
        for (int e = 0; e < NE; e++) { g_off[e] = s; s += g_cnt[e]; }
    }
}

__global__ void place_kernel() {
    int t = blockIdx.x * blockDim.x + threadIdx.x;
    if (t >= S) return;
    #pragma unroll
    for (int k2 = 0; k2 < 2; k2++) {
        int e = g_topi[t*2 + k2];
        int slot = g_off[e] + atomicAdd(&g_cur[e], 1);
        g_atok[slot] = t;
        g_aw[slot] = g_topw[t*2 + k2];
        g_tslot[t*2 + k2] = slot;
    }
}

__global__ void colsum_kernel() {
    int e = blockIdx.x; int tid = threadIdx.x;
    float s = 0.f;
    for (int t = tid; t < S; t += 256) s += g_probs[t * NE + e];
    __shared__ float red[256];
    red[tid] = s; __syncthreads();
    for (int st = 128; st; st >>= 1) { if (tid < st) red[tid] += red[tid + st]; __syncthreads(); }
    if (tid == 0) g_colsum[e] = red[0];
}

__global__ void combine_kernel(float* __restrict__ out) {
    int t = blockIdx.x; int c = threadIdx.x;
    int s0 = g_tslot[t*2], s1 = g_tslot[t*2+1];
    float w0 = g_aw[s0], w1 = g_aw[s1];
    const float4* x14 = (const float4*)(g_x1 + (size_t)t * D);
    const float4* y0  = (const float4*)(g_y + (size_t)s0 * D);
    const float4* y1  = (const float4*)(g_y + (size_t)s1 * D);
    float4 a = x14[c], b = y0[c], d2 = y1[c];
    float4 o;
    o.x = a.x + w0*b.x + w1*d2.x; o.y = a.y + w0*b.y + w1*d2.y;
    o.z = a.z + w0*b.z + w1*d2.z; o.w = a.w + w0*b.w + w1*d2.w;
    ((float4*)out)[(size_t)t * (D/4) + c] = o;
}

__global__ void aux_kernel(float* __restrict__ out, int out_size) {
    int tid = threadIdx.x;
    float v = (tid < NE) ? g_colsum[tid] * g_colsum[tid] : 0.f;
    #pragma unroll
    for (int s = 16; s; s >>= 1) v += __shfl_xor_sync(0xffffffffu, v, s);
    if (tid == 0) {
        float aux = v * (1.0f / (float)NE) * 1e-5f;
        for (int idx = S * D; idx < out_size; ++idx) out[idx] = aux;
    }
}

// ---------------- launch -----------------------------------------------------
extern "C" void kernel_launch(void* const* d_in, const int* in_sizes, int n_in,
                              void* d_out, int out_size) {
    const float* x    = (const float*)d_in[0];
    const float* n1w  = (const float*)d_in[1];
    const float* wq   = (const float*)d_in[2];
    const float* bq   = (const float*)d_in[3];
    const float* wk   = (const float*)d_in[4];
    const float* bk   = (const float*)d_in[5];
    const float* wv   = (const float*)d_in[6];
    const float* bv   = (const float*)d_in[7];
    const float* wo   = (const float*)d_in[8];
    const float* bo   = (const float*)d_in[9];
    const float* sink = (const float*)d_in[10];
    const float* n2w  = (const float*)d_in[11];
    const float* rw   = (const float*)d_in[12];
    const float* rb   = (const float*)d_in[13];
    const float* w1   = (const float*)d_in[14];
    const float* b1   = (const float*)d_in[15];
    const float* w2   = (const float*)d_in[16];
    const float* b2   = (const float*)d_in[17];
    float* out = (float*)d_out;

    void* p;
    cudaGetSymbolAddress(&p, g_h);    float* hB    = (float*)p;
    cudaGetSymbolAddress(&p, g_x1);   float* x1B   = (float*)p;
    cudaGetSymbolAddress(&p, g_h2);   float* h2B   = (float*)p;

    cudaFuncSetAttribute(qkv_kernel,  cudaFuncAttributeMaxDynamicSharedMemorySize, SPLIT_SMEM_BYTES);
    cudaFuncSetAttribute(oproj_kernel, cudaFuncAttributeMaxDynamicSharedMemorySize, SPLIT_SMEM_BYTES);

    // 1) RMSNorm1
    rmsnorm_kernel<<<S, 256>>>(x, n1w, hB);

    // 2) fused QKV projections (3xTF32 tensor cores)
    qkv_kernel<<<dim3(12, 32), 256, SPLIT_SMEM_BYTES>>>(hB, wq, bq, wk, bk, wv, bv);

    // 3) sliding-window attention with sink
    attn_kernel<<<dim3(S/8, NH), 256>>>(sink);

    // 4) O-proj + residual (3xTF32)
    oproj_kernel<<<dim3(8, 32), 256, SPLIT_SMEM_BYTES>>>(wo, bo, x);

    // 5) RMSNorm2
    rmsnorm_kernel<<<S, 256>>>(x1B, n2w, h2B);

    // 6) router + grouping
    zero_kernel<<<1, 32>>>();
    router_kernel<<<S/8, 256>>>(rw, rb);
    offsets_kernel<<<1, 32>>>();
    place_kernel<<<8, 256>>>();
    colsum_kernel<<<NE, 256>>>();

    // 7) grouped MoE GEMMs (top-2 only, 1xTF32)
    moe1_kernel<<<dim3(4, 32, NE), 256>>>(h2B, w1, b1);
    moe2_kernel<<<dim3(8, 32, NE), 256>>>(w2, b2);

    // 8) combine + residual, aux loss
    combine_kernel<<<S, 256>>>(out);
    aux_kernel<<<1, 32>>>(out, out_size);
}

// round 7
// speedup vs baseline: 2.3655x; 1.1878x over previous
#include <cuda_runtime.h>
#include <math.h>
#include <stdint.h>

#define S 2048
#define D 1024
#define NH 8
#define NKV 2
#define HD 128
#define WS 64
#define NE 16
#define HDIM 512
#define NA (S*2)

// ---------------- scratch (static device globals; no allocation) ------------
__device__ float g_h[S*D];
__device__ float g_q[S*D];
__device__ float g_k[S*NKV*HD];
__device__ float g_v[S*NKV*HD];
__device__ float g_attn[S*D];
__device__ float g_x1[S*D];
__device__ float g_h2[S*D];
__device__ float g_probs[S*NE];
__device__ float g_topw[S*2];
__device__ int   g_topi[S*2];
__device__ int   g_cnt[NE];
__device__ int   g_off[NE];
__device__ int   g_cur[NE];
__device__ int   g_atok[NA];
__device__ float g_aw[NA];
__device__ int   g_tslot[S*2];
__device__ float g_hmid[NA*HDIM];
__device__ float g_y[NA*D];
__device__ float g_colsum[NE];

// ---------------- RMSNorm: one block per row, 256 threads x float4 ----------
__global__ void rmsnorm_kernel(const float* __restrict__ x,
                               const float* __restrict__ w,
                               float* __restrict__ o) {
    int row = blockIdx.x;
    int tid = threadIdx.x;
    const float4* x4 = (const float4*)(x + (size_t)row * D);
    float4 v = x4[tid];
    float ss = v.x*v.x + v.y*v.y + v.z*v.z + v.w*v.w;
    __shared__ float red[8];
    #pragma unroll
    for (int s = 16; s; s >>= 1) ss += __shfl_xor_sync(0xffffffffu, ss, s);
    if ((tid & 31) == 0) red[tid >> 5] = ss;
    __syncthreads();
    if (tid < 32) {
        float t = (tid < 8) ? red[tid] : 0.f;
        #pragma unroll
        for (int s = 4; s; s >>= 1) t += __shfl_xor_sync(0xffffffffu, t, s);
        if (tid == 0) red[0] = t;
    }
    __syncthreads();
    float r = rsqrtf(red[0] * (1.0f / (float)D) + 1e-6f);
    const float4* w4 = (const float4*)w;
    float4 wv = w4[tid];
    float4 out;
    out.x = v.x * r * wv.x; out.y = v.y * r * wv.y;
    out.z = v.z * r * wv.z; out.w = v.w * r * wv.w;
    ((float4*)(o + (size_t)row * D))[tid] = out;
}

// =============================================================================
// Common GEMM geometry: CTA tile 64x128x16, 8 warps (2x4), warp tile 32x32.
// =============================================================================
#define BM 64
#define BN 128
#define BKT 16

// ---- tf32 path (MoE, 1-term) ------------------------------------------------
#define ASTR 20
#define BSTR 136
#define APLANE (BM*ASTR)   // 1280 words
#define BPLANE (BKT*BSTR)  // 2176 words

// ---- bf16 path (attention GEMMs, 3-term split) ------------------------------
#define ASTRH 12                 // 8 packed k-pairs + 4 pad
#define BSTRH 136
#define APLANEH (BM*ASTRH)       // 768 words
#define BPLANEH (8*BSTRH)        // 1088 words (8 k-pair rows)
#define HSTAGE (2*APLANEH + 2*BPLANEH)   // hiA, loA, hiB, loB = 3712 words

static __device__ __forceinline__ uint32_t f2tf(float x) {
    uint32_t r; asm("cvt.rna.tf32.f32 %0, %1;" : "=r"(r) : "f"(x)); return r;
}

// pack two floats into bf16x2: lo_k -> bits[15:0], hi_k -> bits[31:16]
static __device__ __forceinline__ uint32_t packbf2(float lo_k, float hi_k) {
    uint32_t r; asm("cvt.rn.bf16x2.f32 %0, %1, %2;" : "=r"(r) : "f"(hi_k), "f"(lo_k));
    return r;
}

static __device__ __forceinline__ void mma8(float* d, const uint32_t* a, const uint32_t* b) {
    asm volatile("mma.sync.aligned.m16n8k8.row.col.f32.tf32.tf32.f32 "
        "{%0,%1,%2,%3}, {%4,%5,%6,%7}, {%8,%9}, {%0,%1,%2,%3};\n"
        : "+f"(d[0]), "+f"(d[1]), "+f"(d[2]), "+f"(d[3])
        : "r"(a[0]), "r"(a[1]), "r"(a[2]), "r"(a[3]), "r"(b[0]), "r"(b[1]));
}

static __device__ __forceinline__ void mma16(float* d, const uint32_t* a, const uint32_t* b) {
    asm volatile("mma.sync.aligned.m16n8k16.row.col.f32.bf16.bf16.f32 "
        "{%0,%1,%2,%3}, {%4,%5,%6,%7}, {%8,%9}, {%0,%1,%2,%3};\n"
        : "+f"(d[0]), "+f"(d[1]), "+f"(d[2]), "+f"(d[3])
        : "r"(a[0]), "r"(a[1]), "r"(a[2]), "r"(a[3]), "r"(b[0]), "r"(b[1]));
}

// shared epilogue: bias [+resid][silu], write C
template<int XEPI>
static __device__ __forceinline__ void gemm_epilogue(
    float acc[2][4][4], const float* __restrict__ bias, const float* __restrict__ resid,
    float* __restrict__ C, int M, int Nld, int m0, int n0, int wm, int wn, int g, int tg)
{
    #pragma unroll
    for (int i = 0; i < 2; i++) {
        int rr0 = m0 + wm + i*16 + g;
        int rr1 = rr0 + 8;
        #pragma unroll
        for (int j = 0; j < 4; j++) {
            int c = n0 + wn + j*8 + tg*2;
            float b0v = bias[c], b1v = bias[c+1];
            if (rr0 < M) {
                float t0 = acc[i][j][0] + b0v;
                float t1 = acc[i][j][1] + b1v;
                if (XEPI == 1) {
                    t0 += resid[(size_t)rr0*Nld + c];
                    t1 += resid[(size_t)rr0*Nld + c + 1];
                }
                if (XEPI == 2) {
                    t0 = t0 / (1.f + expf(-t0));
                    t1 = t1 / (1.f + expf(-t1));
                }
                float2 o; o.x = t0; o.y = t1;
                *(float2*)&C[(size_t)rr0*Nld + c] = o;
            }
            if (rr1 < M) {
                float t0 = acc[i][j][2] + b0v;
                float t1 = acc[i][j][3] + b1v;
                if (XEPI == 1) {
                    t0 += resid[(size_t)rr1*Nld + c];
                    t1 += resid[(size_t)rr1*Nld + c + 1];
                }
                if (XEPI == 2) {
                    t0 = t0 / (1.f + expf(-t0));
                    t1 = t1 / (1.f + expf(-t1));
                }
                float2 o; o.x = t0; o.y = t1;
                *(float2*)&C[(size_t)rr1*Nld + c] = o;
            }
        }
    }
}

// =============================================================================
// bf16 3-term split GEMM core (attention path, ~fp32 accuracy)
// smem stage layout: [Ahi|Alo|Bhi|Blo]
// =============================================================================
static __device__ __forceinline__ void store_stage_bf16(
    uint32_t* base, float4 ra, float4 rb0v, float4 rb1v,
    int arow, int pa0, int pr, int bc)
{
    // A: rows=arow, k pairs pa0, pa0+1
    uint32_t p0 = packbf2(ra.x, ra.y);
    uint32_t p1 = packbf2(ra.z, ra.w);
    base[arow*ASTRH + pa0]     = p0;
    base[arow*ASTRH + pa0 + 1] = p1;
    float l0 = ra.x - __uint_as_float(p0 << 16);
    float l1 = ra.y - __uint_as_float(p0 & 0xffff0000u);
    float l2 = ra.z - __uint_as_float(p1 << 16);
    float l3 = ra.w - __uint_as_float(p1 & 0xffff0000u);
    base[APLANEH + arow*ASTRH + pa0]     = packbf2(l0, l1);
    base[APLANEH + arow*ASTRH + pa0 + 1] = packbf2(l2, l3);
    // B: pair row pr packs k=2pr (lo half) and k=2pr+1 (hi half), 4 cols
    float b0a[4] = {rb0v.x, rb0v.y, rb0v.z, rb0v.w};
    float b1a[4] = {rb1v.x, rb1v.y, rb1v.z, rb1v.w};
    uint32_t hp[4], lp[4];
    #pragma unroll
    for (int j = 0; j < 4; j++) {
        uint32_t h = packbf2(b0a[j], b1a[j]);
        hp[j] = h;
        float ll0 = b0a[j] - __uint_as_float(h << 16);
        float ll1 = b1a[j] - __uint_as_float(h & 0xffff0000u);
        lp[j] = packbf2(ll0, ll1);
    }
    *(uint4*)&base[2*APLANEH + pr*BSTRH + bc] = make_uint4(hp[0], hp[1], hp[2], hp[3]);
    *(uint4*)&base[2*APLANEH + BPLANEH + pr*BSTRH + bc] = make_uint4(lp[0], lp[1], lp[2], lp[3]);
}

template<int XEPI>
static __device__ __forceinline__ void gemm_core_bf16(
    uint32_t* Hsm,
    const float* __restrict__ A, const float* __restrict__ B,
    const float* __restrict__ bias, const float* __restrict__ resid,
    float* __restrict__ C, int M, int Nld, int K, int m0, int n0)
{
    int tid = threadIdx.x;
    int arow = tid >> 2;
    int ac = (tid & 3) * 4;         // k offset of A load
    int pa0 = (tid & 3) * 2;        // k-pair index
    int r0 = m0 + arow;
    bool v0 = r0 < M;
    const float* Ar0 = A + (size_t)(v0 ? r0 : 0) * K;
    int pr = tid >> 5;              // k-pair row of B (0..7)
    int bc = (tid & 31) * 4;
    const float* Bp0 = B + (size_t)(2*pr) * Nld + n0 + bc;
    const float* Bp1 = Bp0 + Nld;

    int lane = tid & 31, g = lane >> 2, tg = lane & 3;
    int wm = (tid >> 7) * 32;
    int wn = ((tid >> 5) & 3) * 32;

    float acc[2][4][4];
    #pragma unroll
    for (int i = 0; i < 2; i++)
        #pragma unroll
        for (int j = 0; j < 4; j++)
            #pragma unroll
            for (int c = 0; c < 4; c++) acc[i][j][c] = 0.f;

    float4 ra   = v0 ? *(const float4*)(Ar0 + ac) : make_float4(0.f,0.f,0.f,0.f);
    float4 rb0v = *(const float4*)(Bp0);
    float4 rb1v = *(const float4*)(Bp1);
    store_stage_bf16(Hsm, ra, rb0v, rb1v, arow, pa0, pr, bc);
    __syncthreads();
    int cur = 0;

    for (int k0 = 0; k0 < K; k0 += BKT) {
        int kn = k0 + BKT;
        bool more = kn < K;
        if (more) {
            ra   = v0 ? *(const float4*)(Ar0 + kn + ac) : make_float4(0.f,0.f,0.f,0.f);
            rb0v = *(const float4*)(Bp0 + (size_t)kn * Nld);
            rb1v = *(const float4*)(Bp1 + (size_t)kn * Nld);
        }
        const uint32_t* Ah = Hsm + cur * HSTAGE;
        const uint32_t* Al = Ah + APLANEH;
        const uint32_t* Bh = Ah + 2*APLANEH;
        const uint32_t* Bl = Bh + BPLANEH;

        uint32_t ah[2][4], al[2][4], bh[4][2], bl[4][2];
        #pragma unroll
        for (int i = 0; i < 2; i++) {
            int mb = wm + i*16 + g;
            ah[i][0] = Ah[mb*ASTRH + tg];       ah[i][1] = Ah[(mb+8)*ASTRH + tg];
            ah[i][2] = Ah[mb*ASTRH + tg+4];     ah[i][3] = Ah[(mb+8)*ASTRH + tg+4];
            al[i][0] = Al[mb*ASTRH + tg];       al[i][1] = Al[(mb+8)*ASTRH + tg];
            al[i][2] = Al[mb*ASTRH + tg+4];     al[i][3] = Al[(mb+8)*ASTRH + tg+4];
        }
        #pragma unroll
        for (int j = 0; j < 4; j++) {
            int nb = wn + j*8 + g;
            bh[j][0] = Bh[tg*BSTRH + nb];       bh[j][1] = Bh[(tg+4)*BSTRH + nb];
            bl[j][0] = Bl[tg*BSTRH + nb];       bl[j][1] = Bl[(tg+4)*BSTRH + nb];
        }
        #pragma unroll
        for (int i = 0; i < 2; i++)
            #pragma unroll
            for (int j = 0; j < 4; j++) mma16(acc[i][j], ah[i], bh[j]);
        #pragma unroll
        for (int i = 0; i < 2; i++)
            #pragma unroll
            for (int j = 0; j < 4; j++) mma16(acc[i][j], ah[i], bl[j]);
        #pragma unroll
        for (int i = 0; i < 2; i++)
            #pragma unroll
            for (int j = 0; j < 4; j++) mma16(acc[i][j], al[i], bh[j]);

        if (more) {
            store_stage_bf16(Hsm + (cur ^ 1) * HSTAGE, ra, rb0v, rb1v, arow, pa0, pr, bc);
            __syncthreads();
            cur ^= 1;
        }
    }
    gemm_epilogue<XEPI>(acc, bias, resid, C, M, Nld, m0, n0, wm, wn, g, tg);
}

// =============================================================================
// tf32 single-term GEMM core (MoE path) — unchanged from R6
// =============================================================================
#define STORE_TILE(stg) do { \
    uint32_t* Ab = Asm + (stg) * APLANE; \
    uint32_t* Bb = Bsm + (stg) * BPLANE; \
    float av[4] = {ra.x, ra.y, ra.z, ra.w}; \
    _Pragma("unroll") \
    for (int j = 0; j < 4; j++) Ab[arow*ASTR + ac + j] = f2tf(av[j]); \
    float bvv[8] = {rb0v.x, rb0v.y, rb0v.z, rb0v.w, rb1v.x, rb1v.y, rb1v.z, rb1v.w}; \
    _Pragma("unroll") \
    for (int j = 0; j < 8; j++) { \
        int row = (j < 4) ? brow : (brow + 8); \
        Bb[row*BSTR + bc + (j & 3)] = f2tf(bvv[j]); \
    } \
} while (0)

template<int XEPI, int XGATHER>
static __device__ __forceinline__ void gemm_core_tf32(
    uint32_t* Asm, uint32_t* Bsm,
    const float* __restrict__ A, const float* __restrict__ B,
    const float* __restrict__ bias, const float* __restrict__ resid,
    float* __restrict__ C, int M, int Nld, int K, int m0, int n0,
    const int* __restrict__ rowidx)
{
    int tid = threadIdx.x;
    int arow = tid >> 2;
    int ac = (tid & 3) * 4;
    int r0 = m0 + arow;
    bool v0 = r0 < M;
    int gr0 = v0 ? (XGATHER ? rowidx[r0] : r0) : 0;
    const float* Ar0 = A + (size_t)gr0 * K;
    int brow = tid >> 5;
    int bc = (tid & 31) * 4;
    const float* Bp0 = B + (size_t)brow * Nld + n0 + bc;
    const float* Bp1 = Bp0 + (size_t)8 * Nld;

    int lane = tid & 31, g = lane >> 2, tg = lane & 3;
    int wm = (tid >> 7) * 32;
    int wn = ((tid >> 5) & 3) * 32;

    float acc[2][4][4];
    #pragma unroll
    for (int i = 0; i < 2; i++)
        #pragma unroll
        for (int j = 0; j < 4; j++)
            #pragma unroll
            for (int c = 0; c < 4; c++) acc[i][j][c] = 0.f;

    float4 ra  = v0 ? *(const float4*)(Ar0 + ac) : make_float4(0.f,0.f,0.f,0.f);
    float4 rb0v = *(const float4*)(Bp0);
    float4 rb1v = *(const float4*)(Bp1);
    STORE_TILE(0);
    __syncthreads();
    int cur = 0;

    for (int k0 = 0; k0 < K; k0 += BKT) {
        int kn = k0 + BKT;
        bool more = kn < K;
        if (more) {
            ra  = v0 ? *(const float4*)(Ar0 + kn + ac) : make_float4(0.f,0.f,0.f,0.f);
            rb0v = *(const float4*)(Bp0 + (size_t)kn * Nld);
            rb1v = *(const float4*)(Bp1 + (size_t)kn * Nld);
        }
        const uint32_t* Ab = Asm + cur * APLANE;
        const uint32_t* Bb = Bsm + cur * BPLANE;
        #pragma unroll
        for (int ks = 0; ks < BKT; ks += 8) {
            uint32_t af[2][4], bf[4][2];
            #pragma unroll
            for (int i = 0; i < 2; i++) {
                int mb = wm + i*16 + g;
                af[i][0] = Ab[mb*ASTR + ks+tg];
                af[i][1] = Ab[(mb+8)*ASTR + ks+tg];
                af[i][2] = Ab[mb*ASTR + ks+tg+4];
                af[i][3] = Ab[(mb+8)*ASTR + ks+tg+4];
            }
            #pragma unroll
            for (int j = 0; j < 4; j++) {
                int nb = wn + j*8 + g;
                bf[j][0] = Bb[(ks+tg)*BSTR + nb];
                bf[j][1] = Bb[(ks+tg+4)*BSTR + nb];
            }
            #pragma unroll
            for (int i = 0; i < 2; i++)
                #pragma unroll
                for (int j = 0; j < 4; j++) mma8(acc[i][j], af[i], bf[j]);
        }
        if (more) {
            STORE_TILE(cur ^ 1);
            __syncthreads();
            cur ^= 1;
        }
    }
    gemm_epilogue<XEPI>(acc, bias, resid, C, M, Nld, m0, n0, wm, wn, g, tg);
}

// ---- fused QKV (bf16 3-term): grid (12, 32) ---------------------------------
__global__ void __launch_bounds__(256, 2) qkv_kernel(
    const float* __restrict__ h,
    const float* __restrict__ wq, const float* __restrict__ bq,
    const float* __restrict__ wk, const float* __restrict__ bk,
    const float* __restrict__ wv, const float* __restrict__ bv)
{
    __shared__ __align__(16) uint32_t Hsm[2*HSTAGE];
    int x = blockIdx.x, m0 = blockIdx.y * BM;
    if (x < 8)
        gemm_core_bf16<0>(Hsm, h, wq, bq, nullptr, g_q, S, 1024, 1024, m0, x*128);
    else if (x < 10)
        gemm_core_bf16<0>(Hsm, h, wk, bk, nullptr, g_k, S, 256, 1024, m0, (x-8)*128);
    else
        gemm_core_bf16<0>(Hsm, h, wv, bv, nullptr, g_v, S, 256, 1024, m0, (x-10)*128);
}

// ---- O-proj + residual (bf16 3-term): grid (8, 32) --------------------------
__global__ void __launch_bounds__(256, 2) oproj_kernel(
    const float* __restrict__ wo, const float* __restrict__ bo,
    const float* __restrict__ x)
{
    __shared__ __align__(16) uint32_t Hsm[2*HSTAGE];
    gemm_core_bf16<1>(Hsm, g_attn, wo, bo, x, g_x1, S, 1024, 1024,
                      blockIdx.y*BM, blockIdx.x*BN);
}

// ---- MoE expert GEMMs (1xTF32, grouped, static 2-stage smem) ----------------
__global__ void __launch_bounds__(256, 2) moe1_kernel(
    const float* __restrict__ h2, const float* __restrict__ w1,
    const float* __restrict__ b1)
{
    int e = blockIdx.z;
    int M = g_cnt[e];
    int m0 = blockIdx.y * BM;
    if (m0 >= M) return;
    int o = g_off[e];
    __shared__ uint32_t sA[2*APLANE];
    __shared__ uint32_t sB[2*BPLANE];
    gemm_core_tf32<2,1>(sA, sB, h2, w1 + (size_t)e*1024*512, b1 + (size_t)e*512,
                        nullptr, g_hmid + (size_t)o*512, M, 512, 1024,
                        m0, blockIdx.x*BN, g_atok + o);
}

__global__ void __launch_bounds__(256, 2) moe2_kernel(
    const float* __restrict__ w2, const float* __restrict__ b2)
{
    int e = blockIdx.z;
    int M = g_cnt[e];
    int m0 = blockIdx.y * BM;
    if (m0 >= M) return;
    int o = g_off[e];
    __shared__ uint32_t sA[2*APLANE];
    __shared__ uint32_t sB[2*BPLANE];
    gemm_core_tf32<0,0>(sA, sB, g_hmid + (size_t)o*512, w2 + (size_t)e*512*1024,
                        b2 + (size_t)e*1024, nullptr, g_y + (size_t)o*1024,
                        M, 1024, 512, m0, blockIdx.x*BN, nullptr);
}

// ---------------- sliding-window attention, 1 warp = 1 query row ------------
__global__ void attn_kernel(const float* __restrict__ sinkp) {
    int warp = threadIdx.x >> 5, lane = threadIdx.x & 31;
    int i = blockIdx.x * 8 + warp;
    int h = blockIdx.y;
    int kvh = h >> 2;  // NH/NKV = 4
    const float scale = 0.08838834764831845f;  // 1/sqrt(128)

    float qr[4];
    const float* qp = g_q + (size_t)i * D + h * HD;
    #pragma unroll
    for (int c = 0; c < 4; c++) qr[c] = qp[lane + 32 * c];

    int jstart = (i >= (WS - 1)) ? (i - (WS - 1)) : 0;
    int cnt = i - jstart + 1;

    float s0 = -1e30f, s1 = -1e30f;
    for (int jj = 0; jj < cnt; ++jj) {
        const float* kp = g_k + (size_t)(jstart + jj) * (NKV * HD) + kvh * HD;
        float p = qr[0]*kp[lane] + qr[1]*kp[lane+32] + qr[2]*kp[lane+64] + qr[3]*kp[lane+96];
        #pragma unroll
        for (int s = 16; s; s >>= 1) p += __shfl_xor_sync(0xffffffffu, p, s);
        p *= scale;
        if ((jj & 31) == lane) { if (jj < 32) s0 = p; else s1 = p; }
    }
    float sink = *sinkp;
    float m = fmaxf(s0, s1);
    #pragma unroll
    for (int s = 16; s; s >>= 1) m = fmaxf(m, __shfl_xor_sync(0xffffffffu, m, s));
    m = fmaxf(m, sink);
    float e0 = expf(s0 - m), e1 = expf(s1 - m);
    float dsum = e0 + e1;
    #pragma unroll
    for (int s = 16; s; s >>= 1) dsum += __shfl_xor_sync(0xffffffffu, dsum, s);
    dsum += expf(sink - m);
    float inv = 1.f / dsum;

    float o0 = 0.f, o1 = 0.f, o2 = 0.f, o3 = 0.f;
    for (int jj = 0; jj < cnt; ++jj) {
        float pv = (jj < 32) ? e0 : e1;
        float p = __shfl_sync(0xffffffffu, pv, jj & 31);
        const float* vp = g_v + (size_t)(jstart + jj) * (NKV * HD) + kvh * HD;
        o0 += p * vp[lane];      o1 += p * vp[lane + 32];
        o2 += p * vp[lane + 64]; o3 += p * vp[lane + 96];
    }
    float* op = g_attn + (size_t)i * D + h * HD;
    op[lane]      = o0 * inv; op[lane + 32] = o1 * inv;
    op[lane + 64] = o2 * inv; op[lane + 96] = o3 * inv;
}

// ---------------- router: 1 warp = 1 token ----------------------------------
__global__ void router_kernel(const float* __restrict__ rw, const float* __restrict__ rb) {
    int warp = threadIdx.x >> 5, lane = threadIdx.x & 31;
    int t = blockIdx.x * 8 + warp;
    float acc[NE];
    #pragma unroll
    for (int e = 0; e < NE; e++) acc[e] = 0.f;
    const float* xr = g_h2 + (size_t)t * D;
    for (int d = lane; d < D; d += 32) {
        float xv = xr[d];
        const float* rr = rw + d * NE;
        #pragma unroll
        for (int e = 0; e < NE; e++) acc[e] += xv * rr[e];
    }
    #pragma unroll
    for (int e = 0; e < NE; e++) {
        float a = acc[e];
        #pragma unroll
        for (int s = 16; s; s >>= 1) a += __shfl_xor_sync(0xffffffffu, a, s);
        acc[e] = a;
    }
    if (lane == 0) {
        float logit[NE]; float m = -1e30f;
        #pragma unroll
        for (int e = 0; e < NE; e++) { logit[e] = (acc[e] + rb[e]) * 10.f; m = fmaxf(m, logit[e]); }
        float pe[NE]; float ssum = 0.f;
        #pragma unroll
        for (int e = 0; e < NE; e++) { pe[e] = expf(logit[e] - m); ssum += pe[e]; }
        float invs = 1.f / ssum;
        #pragma unroll
        for (int e = 0; e < NE; e++) g_probs[t * NE + e] = pe[e] * invs;
        int i0 = 0; float v0 = logit[0];
        #pragma unroll
        for (int e = 1; e < NE; e++) if (logit[e] > v0) { v0 = logit[e]; i0 = e; }
        int i1 = -1; float v1 = -1e30f;
        #pragma unroll
        for (int e = 0; e < NE; e++) if (e != i0 && logit[e] > v1) { v1 = logit[e]; i1 = e; }
        float ex = expf(v1 - v0);
        float w0 = 1.f / (1.f + ex);
        g_topi[t*2] = i0; g_topi[t*2+1] = i1;
        g_topw[t*2] = w0; g_topw[t*2+1] = 1.f - w0;
        atomicAdd(&g_cnt[i0], 1); atomicAdd(&g_cnt[i1], 1);
    }
}

__global__ void zero_kernel() {
    int t = threadIdx.x;
    if (t < NE) { g_cnt[t] = 0; g_cur[t] = 0; }
}

__global__ void offsets_kernel() {
    if (threadIdx.x == 0) {
        int s = 0;
        for (int e = 0; e < NE; e++) { g_off[e] = s; s += g_cnt[e]; }
    }
}

__global__ void place_kernel() {
    int t = blockIdx.x * blockDim.x + threadIdx.x;
    if (t >= S) return;
    #pragma unroll
    for (int k2 = 0; k2 < 2; k2++) {
        int e = g_topi[t*2 + k2];
        int slot = g_off[e] + atomicAdd(&g_cur[e], 1);
        g_atok[slot] = t;
        g_aw[slot] = g_topw[t*2 + k2];
        g_tslot[t*2 + k2] = slot;
    }
}

__global__ void colsum_kernel() {
    int e = blockIdx.x; int tid = threadIdx.x;
    float s = 0.f;
    for (int t = tid; t < S; t += 256) s += g_probs[t * NE + e];
    __shared__ float red[256];
    red[tid] = s; __syncthreads();
    for (int st = 128; st; st >>= 1) { if (tid < st) red[tid] += red[tid + st]; __syncthreads(); }
    if (tid == 0) g_colsum[e] = red[0];
}

__global__ void combine_kernel(float* __restrict__ out) {
    int t = blockIdx.x; int c = threadIdx.x;
    int s0 = g_tslot[t*2], s1 = g_tslot[t*2+1];
    float w0 = g_aw[s0], w1 = g_aw[s1];
    const float4* x14 = (const float4*)(g_x1 + (size_t)t * D);
    const float4* y0  = (const float4*)(g_y + (size_t)s0 * D);
    const float4* y1  = (const float4*)(g_y + (size_t)s1 * D);
    float4 a = x14[c], b = y0[c], d2 = y1[c];
    float4 o;
    o.x = a.x + w0*b.x + w1*d2.x; o.y = a.y + w0*b.y + w1*d2.y;
    o.z = a.z + w0*b.z + w1*d2.z; o.w = a.w + w0*b.w + w1*d2.w;
    ((float4*)out)[(size_t)t * (D/4) + c] = o;
}

__global__ void aux_kernel(float* __restrict__ out, int out_size) {
    int tid = threadIdx.x;
    float v = (tid < NE) ? g_colsum[tid] * g_colsum[tid] : 0.f;
    #pragma unroll
    for (int s = 16; s; s >>= 1) v += __shfl_xor_sync(0xffffffffu, v, s);
    if (tid == 0) {
        float aux = v * (1.0f / (float)NE) * 1e-5f;
        for (int idx = S * D; idx < out_size; ++idx) out[idx] = aux;
    }
}

// ---------------- launch -----------------------------------------------------
extern "C" void kernel_launch(void* const* d_in, const int* in_sizes, int n_in,
                              void* d_out, int out_size) {
    const float* x    = (const float*)d_in[0];
    const float* n1w  = (const float*)d_in[1];
    const float* wq   = (const float*)d_in[2];
    const float* bq   = (const float*)d_in[3];
    const float* wk   = (const float*)d_in[4];
    const float* bk   = (const float*)d_in[5];
    const float* wv   = (const float*)d_in[6];
    const float* bv   = (const float*)d_in[7];
    const float* wo   = (const float*)d_in[8];
    const float* bo   = (const float*)d_in[9];
    const float* sink = (const float*)d_in[10];
    const float* n2w  = (const float*)d_in[11];
    const float* rw   = (const float*)d_in[12];
    const float* rb   = (const float*)d_in[13];
    const float* w1   = (const float*)d_in[14];
    const float* b1   = (const float*)d_in[15];
    const float* w2   = (const float*)d_in[16];
    const float* b2   = (const float*)d_in[17];
    float* out = (float*)d_out;

    void* p;
    cudaGetSymbolAddress(&p, g_h);    float* hB    = (float*)p;
    cudaGetSymbolAddress(&p, g_x1);   float* x1B   = (float*)p;
    cudaGetSymbolAddress(&p, g_h2);   float* h2B   = (float*)p;

    // 1) RMSNorm1
    rmsnorm_kernel<<<S, 256>>>(x, n1w, hB);

    // 2) fused QKV projections (bf16x2 3-term tensor cores)
    qkv_kernel<<<dim3(12, 32), 256>>>(hB, wq, bq, wk, bk, wv, bv);

    // 3) sliding-window attention with sink
    attn_kernel<<<dim3(S/8, NH), 256>>>(sink);

    // 4) O-proj + residual (bf16x2 3-term)
    oproj_kernel<<<dim3(8, 32), 256>>>(wo, bo, x);

    // 5) RMSNorm2
    rmsnorm_kernel<<<S, 256>>>(x1B, n2w, h2B);

    // 6) router + grouping
    zero_kernel<<<1, 32>>>();
    router_kernel<<<S/8, 256>>>(rw, rb);
    offsets_kernel<<<1, 32>>>();
    place_kernel<<<8, 256>>>();
    colsum_kernel<<<NE, 256>>>();

    // 7) grouped MoE GEMMs (top-2 only, 1xTF32)
    moe1_kernel<<<dim3(4, 32, NE), 256>>>(h2B, w1, b1);
    moe2_kernel<<<dim3(8, 32, NE), 256>>>(w2, b2);

    // 8) combine + residual, aux loss
    combine_kernel<<<S, 256>>>(out);
    aux_kernel<<<1, 32>>>(out, out_size);
}

// round 8
// speedup vs baseline: 2.3751x; 1.0041x over previous
#include <cuda_runtime.h>
#include <math.h>
#include <stdint.h>

#define S 2048
#define D 1024
#define NH 8
#define NKV 2
#define HD 128
#define WS 64
#define NE 16
#define HDIM 512
#define NA (S*2)

// ---------------- scratch (static device globals; no allocation) ------------
__device__ float g_h[S*D];
__device__ float g_q[S*D];
__device__ float g_k[S*NKV*HD];
__device__ float g_v[S*NKV*HD];
__device__ float g_attn[S*D];
__device__ float g_x1[S*D];
__device__ float g_h2[S*D];
__device__ float g_probs[S*NE];
__device__ float g_topw[S*2];
__device__ int   g_topi[S*2];
__device__ int   g_cnt[NE];
__device__ int   g_off[NE];
__device__ int   g_cur[NE];
__device__ int   g_atok[NA];
__device__ float g_aw[NA];
__device__ int   g_tslot[S*2];
__device__ float g_hmid[NA*HDIM];
__device__ float g_y[NA*D];
__device__ float g_colsum[NE];

// ---------------- RMSNorm: one block per row, 256 threads x float4 ----------
__global__ void rmsnorm_kernel(const float* __restrict__ x,
                               const float* __restrict__ w,
                               float* __restrict__ o) {
    int row = blockIdx.x;
    int tid = threadIdx.x;
    const float4* x4 = (const float4*)(x + (size_t)row * D);
    float4 v = x4[tid];
    float ss = v.x*v.x + v.y*v.y + v.z*v.z + v.w*v.w;
    __shared__ float red[8];
    #pragma unroll
    for (int s = 16; s; s >>= 1) ss += __shfl_xor_sync(0xffffffffu, ss, s);
    if ((tid & 31) == 0) red[tid >> 5] = ss;
    __syncthreads();
    if (tid < 32) {
        float t = (tid < 8) ? red[tid] : 0.f;
        #pragma unroll
        for (int s = 4; s; s >>= 1) t += __shfl_xor_sync(0xffffffffu, t, s);
        if (tid == 0) red[0] = t;
    }
    __syncthreads();
    float r = rsqrtf(red[0] * (1.0f / (float)D) + 1e-6f);
    const float4* w4 = (const float4*)w;
    float4 wv = w4[tid];
    float4 out;
    out.x = v.x * r * wv.x; out.y = v.y * r * wv.y;
    out.z = v.z * r * wv.z; out.w = v.w * r * wv.w;
    ((float4*)(o + (size_t)row * D))[tid] = out;
}

// =============================================================================
// Common GEMM geometry: CTA tile 64x128x16, 8 warps (2x4), warp tile 32x32.
// =============================================================================
#define BM 64
#define BN 128
#define BKT 16

// ---- tf32 path (MoE, 1-term) ------------------------------------------------
#define ASTR 20
#define BSTR 136
#define APLANE (BM*ASTR)   // 1280 words
#define BPLANE (BKT*BSTR)  // 2176 words

// ---- bf16 path (attention GEMMs, 3-term split) ------------------------------
#define ASTRH 12                 // 8 packed k-pairs + 4 pad
#define BSTRH 136
#define APLANEH (BM*ASTRH)       // 768 words
#define BPLANEH (8*BSTRH)        // 1088 words (8 k-pair rows)
#define HSTAGE (2*APLANEH + 2*BPLANEH)   // hiA, loA, hiB, loB = 3712 words

static __device__ __forceinline__ uint32_t f2tf(float x) {
    uint32_t r; asm("cvt.rna.tf32.f32 %0, %1;" : "=r"(r) : "f"(x)); return r;
}

// pack two floats into bf16x2: lo_k -> bits[15:0], hi_k -> bits[31:16]
static __device__ __forceinline__ uint32_t packbf2(float lo_k, float hi_k) {
    uint32_t r; asm("cvt.rn.bf16x2.f32 %0, %1, %2;" : "=r"(r) : "f"(hi_k), "f"(lo_k));
    return r;
}

static __device__ __forceinline__ void mma8(float* d, const uint32_t* a, const uint32_t* b) {
    asm volatile("mma.sync.aligned.m16n8k8.row.col.f32.tf32.tf32.f32 "
        "{%0,%1,%2,%3}, {%4,%5,%6,%7}, {%8,%9}, {%0,%1,%2,%3};\n"
        : "+f"(d[0]), "+f"(d[1]), "+f"(d[2]), "+f"(d[3])
        : "r"(a[0]), "r"(a[1]), "r"(a[2]), "r"(a[3]), "r"(b[0]), "r"(b[1]));
}

static __device__ __forceinline__ void mma16(float* d, const uint32_t* a, const uint32_t* b) {
    asm volatile("mma.sync.aligned.m16n8k16.row.col.f32.bf16.bf16.f32 "
        "{%0,%1,%2,%3}, {%4,%5,%6,%7}, {%8,%9}, {%0,%1,%2,%3};\n"
        : "+f"(d[0]), "+f"(d[1]), "+f"(d[2]), "+f"(d[3])
        : "r"(a[0]), "r"(a[1]), "r"(a[2]), "r"(a[3]), "r"(b[0]), "r"(b[1]));
}

// shared epilogue: bias [+resid][silu], write C
template<int XEPI>
static __device__ __forceinline__ void gemm_epilogue(
    float acc[2][4][4], const float* __restrict__ bias, const float* __restrict__ resid,
    float* __restrict__ C, int M, int Nld, int m0, int n0, int wm, int wn, int g, int tg)
{
    #pragma unroll
    for (int i = 0; i < 2; i++) {
        int rr0 = m0 + wm + i*16 + g;
        int rr1 = rr0 + 8;
        #pragma unroll
        for (int j = 0; j < 4; j++) {
            int c = n0 + wn + j*8 + tg*2;
            float b0v = bias[c], b1v = bias[c+1];
            if (rr0 < M) {
                float t0 = acc[i][j][0] + b0v;
                float t1 = acc[i][j][1] + b1v;
                if (XEPI == 1) {
                    t0 += resid[(size_t)rr0*Nld + c];
                    t1 += resid[(size_t)rr0*Nld + c + 1];
                }
                if (XEPI == 2) {
                    t0 = t0 / (1.f + expf(-t0));
                    t1 = t1 / (1.f + expf(-t1));
                }
                float2 o; o.x = t0; o.y = t1;
                *(float2*)&C[(size_t)rr0*Nld + c] = o;
            }
            if (rr1 < M) {
                float t0 = acc[i][j][2] + b0v;
                float t1 = acc[i][j][3] + b1v;
                if (XEPI == 1) {
                    t0 += resid[(size_t)rr1*Nld + c];
                    t1 += resid[(size_t)rr1*Nld + c + 1];
                }
                if (XEPI == 2) {
                    t0 = t0 / (1.f + expf(-t0));
                    t1 = t1 / (1.f + expf(-t1));
                }
                float2 o; o.x = t0; o.y = t1;
                *(float2*)&C[(size_t)rr1*Nld + c] = o;
            }
        }
    }
}

// =============================================================================
// bf16 3-term split GEMM core (attention path, ~fp32 accuracy)
// smem stage layout: [Ahi|Alo|Bhi|Blo]
// =============================================================================
static __device__ __forceinline__ void store_stage_bf16(
    uint32_t* base, float4 ra, float4 rb0v, float4 rb1v,
    int arow, int pa0, int pr, int bc)
{
    // A: rows=arow, k pairs pa0, pa0+1
    uint32_t p0 = packbf2(ra.x, ra.y);
    uint32_t p1 = packbf2(ra.z, ra.w);
    base[arow*ASTRH + pa0]     = p0;
    base[arow*ASTRH + pa0 + 1] = p1;
    float l0 = ra.x - __uint_as_float(p0 << 16);
    float l1 = ra.y - __uint_as_float(p0 & 0xffff0000u);
    float l2 = ra.z - __uint_as_float(p1 << 16);
    float l3 = ra.w - __uint_as_float(p1 & 0xffff0000u);
    base[APLANEH + arow*ASTRH + pa0]     = packbf2(l0, l1);
    base[APLANEH + arow*ASTRH + pa0 + 1] = packbf2(l2, l3);
    // B: pair row pr packs k=2pr (lo half) and k=2pr+1 (hi half), 4 cols
    float b0a[4] = {rb0v.x, rb0v.y, rb0v.z, rb0v.w};
    float b1a[4] = {rb1v.x, rb1v.y, rb1v.z, rb1v.w};
    uint32_t hp[4], lp[4];
    #pragma unroll
    for (int j = 0; j < 4; j++) {
        uint32_t h = packbf2(b0a[j], b1a[j]);
        hp[j] = h;
        float ll0 = b0a[j] - __uint_as_float(h << 16);
        float ll1 = b1a[j] - __uint_as_float(h & 0xffff0000u);
        lp[j] = packbf2(ll0, ll1);
    }
    *(uint4*)&base[2*APLANEH + pr*BSTRH + bc] = make_uint4(hp[0], hp[1], hp[2], hp[3]);
    *(uint4*)&base[2*APLANEH + BPLANEH + pr*BSTRH + bc] = make_uint4(lp[0], lp[1], lp[2], lp[3]);
}

template<int XEPI>
static __device__ __forceinline__ void gemm_core_bf16(
    uint32_t* Hsm,
    const float* __restrict__ A, const float* __restrict__ B,
    const float* __restrict__ bias, const float* __restrict__ resid,
    float* __restrict__ C, int M, int Nld, int K, int m0, int n0)
{
    int tid = threadIdx.x;
    int arow = tid >> 2;
    int ac = (tid & 3) * 4;         // k offset of A load
    int pa0 = (tid & 3) * 2;        // k-pair index
    int r0 = m0 + arow;
    bool v0 = r0 < M;
    const float* Ar0 = A + (size_t)(v0 ? r0 : 0) * K;
    int pr = tid >> 5;              // k-pair row of B (0..7)
    int bc = (tid & 31) * 4;
    const float* Bp0 = B + (size_t)(2*pr) * Nld + n0 + bc;
    const float* Bp1 = Bp0 + Nld;

    int lane = tid & 31, g = lane >> 2, tg = lane & 3;
    int wm = (tid >> 7) * 32;
    int wn = ((tid >> 5) & 3) * 32;

    float acc[2][4][4];
    #pragma unroll
    for (int i = 0; i < 2; i++)
        #pragma unroll
        for (int j = 0; j < 4; j++)
            #pragma unroll
            for (int c = 0; c < 4; c++) acc[i][j][c] = 0.f;

    float4 ra   = v0 ? *(const float4*)(Ar0 + ac) : make_float4(0.f,0.f,0.f,0.f);
    float4 rb0v = *(const float4*)(Bp0);
    float4 rb1v = *(const float4*)(Bp1);
    store_stage_bf16(Hsm, ra, rb0v, rb1v, arow, pa0, pr, bc);
    __syncthreads();
    int cur = 0;

    for (int k0 = 0; k0 < K; k0 += BKT) {
        int kn = k0 + BKT;
        bool more = kn < K;
        if (more) {
            ra   = v0 ? *(const float4*)(Ar0 + kn + ac) : make_float4(0.f,0.f,0.f,0.f);
            rb0v = *(const float4*)(Bp0 + (size_t)kn * Nld);
            rb1v = *(const float4*)(Bp1 + (size_t)kn * Nld);
        }
        const uint32_t* Ah = Hsm + cur * HSTAGE;
        const uint32_t* Al = Ah + APLANEH;
        const uint32_t* Bh = Ah + 2*APLANEH;
        const uint32_t* Bl = Bh + BPLANEH;

        uint32_t ah[2][4], al[2][4], bh[4][2], bl[4][2];
        #pragma unroll
        for (int i = 0; i < 2; i++) {
            int mb = wm + i*16 + g;
            ah[i][0] = Ah[mb*ASTRH + tg];       ah[i][1] = Ah[(mb+8)*ASTRH + tg];
            ah[i][2] = Ah[mb*ASTRH + tg+4];     ah[i][3] = Ah[(mb+8)*ASTRH + tg+4];
            al[i][0] = Al[mb*ASTRH + tg];       al[i][1] = Al[(mb+8)*ASTRH + tg];
            al[i][2] = Al[mb*ASTRH + tg+4];     al[i][3] = Al[(mb+8)*ASTRH + tg+4];
        }
        #pragma unroll
        for (int j = 0; j < 4; j++) {
            int nb = wn + j*8 + g;
            bh[j][0] = Bh[tg*BSTRH + nb];       bh[j][1] = Bh[(tg+4)*BSTRH + nb];
            bl[j][0] = Bl[tg*BSTRH + nb];       bl[j][1] = Bl[(tg+4)*BSTRH + nb];
        }
        #pragma unroll
        for (int i = 0; i < 2; i++)
            #pragma unroll
            for (int j = 0; j < 4; j++) mma16(acc[i][j], ah[i], bh[j]);
        #pragma unroll
        for (int i = 0; i < 2; i++)
            #pragma unroll
            for (int j = 0; j < 4; j++) mma16(acc[i][j], ah[i], bl[j]);
        #pragma unroll
        for (int i = 0; i < 2; i++)
            #pragma unroll
            for (int j = 0; j < 4; j++) mma16(acc[i][j], al[i], bh[j]);

        if (more) {
            store_stage_bf16(Hsm + (cur ^ 1) * HSTAGE, ra, rb0v, rb1v, arow, pa0, pr, bc);
            __syncthreads();
            cur ^= 1;
        }
    }
    gemm_epilogue<XEPI>(acc, bias, resid, C, M, Nld, m0, n0, wm, wn, g, tg);
}

// =============================================================================
// tf32 single-term GEMM core (MoE path) — unchanged from R6
// =============================================================================
#define STORE_TILE(stg) do { \
    uint32_t* Ab = Asm + (stg) * APLANE; \
    uint32_t* Bb = Bsm + (stg) * BPLANE; \
    float av[4] = {ra.x, ra.y, ra.z, ra.w}; \
    _Pragma("unroll") \
    for (int j = 0; j < 4; j++) Ab[arow*ASTR + ac + j] = f2tf(av[j]); \
    float bvv[8] = {rb0v.x, rb0v.y, rb0v.z, rb0v.w, rb1v.x, rb1v.y, rb1v.z, rb1v.w}; \
    _Pragma("unroll") \
    for (int j = 0; j < 8; j++) { \
        int row = (j < 4) ? brow : (brow + 8); \
        Bb[row*BSTR + bc + (j & 3)] = f2tf(bvv[j]); \
    } \
} while (0)

template<int XEPI, int XGATHER>
static __device__ __forceinline__ void gemm_core_tf32(
    uint32_t* Asm, uint32_t* Bsm,
    const float* __restrict__ A, const float* __restrict__ B,
    const float* __restrict__ bias, const float* __restrict__ resid,
    float* __restrict__ C, int M, int Nld, int K, int m0, int n0,
    const int* __restrict__ rowidx)
{
    int tid = threadIdx.x;
    int arow = tid >> 2;
    int ac = (tid & 3) * 4;
    int r0 = m0 + arow;
    bool v0 = r0 < M;
    int gr0 = v0 ? (XGATHER ? rowidx[r0] : r0) : 0;
    const float* Ar0 = A + (size_t)gr0 * K;
    int brow = tid >> 5;
    int bc = (tid & 31) * 4;
    const float* Bp0 = B + (size_t)brow * Nld + n0 + bc;
    const float* Bp1 = Bp0 + (size_t)8 * Nld;

    int lane = tid & 31, g = lane >> 2, tg = lane & 3;
    int wm = (tid >> 7) * 32;
    int wn = ((tid >> 5) & 3) * 32;

    float acc[2][4][4];
    #pragma unroll
    for (int i = 0; i < 2; i++)
        #pragma unroll
        for (int j = 0; j < 4; j++)
            #pragma unroll
            for (int c = 0; c < 4; c++) acc[i][j][c] = 0.f;

    float4 ra  = v0 ? *(const float4*)(Ar0 + ac) : make_float4(0.f,0.f,0.f,0.f);
    float4 rb0v = *(const float4*)(Bp0);
    float4 rb1v = *(const float4*)(Bp1);
    STORE_TILE(0);
    __syncthreads();
    int cur = 0;

    for (int k0 = 0; k0 < K; k0 += BKT) {
        int kn = k0 + BKT;
        bool more = kn < K;
        if (more) {
            ra  = v0 ? *(const float4*)(Ar0 + kn + ac) : make_float4(0.f,0.f,0.f,0.f);
            rb0v = *(const float4*)(Bp0 + (size_t)kn * Nld);
            rb1v = *(const float4*)(Bp1 + (size_t)kn * Nld);
        }
        const uint32_t* Ab = Asm + cur * APLANE;
        const uint32_t* Bb = Bsm + cur * BPLANE;
        #pragma unroll
        for (int ks = 0; ks < BKT; ks += 8) {
            uint32_t af[2][4], bf[4][2];
            #pragma unroll
            for (int i = 0; i < 2; i++) {
                int mb = wm + i*16 + g;
                af[i][0] = Ab[mb*ASTR + ks+tg];
                af[i][1] = Ab[(mb+8)*ASTR + ks+tg];
                af[i][2] = Ab[mb*ASTR + ks+tg+4];
                af[i][3] = Ab[(mb+8)*ASTR + ks+tg+4];
            }
            #pragma unroll
            for (int j = 0; j < 4; j++) {
                int nb = wn + j*8 + g;
                bf[j][0] = Bb[(ks+tg)*BSTR + nb];
                bf[j][1] = Bb[(ks+tg+4)*BSTR + nb];
            }
            #pragma unroll
            for (int i = 0; i < 2; i++)
                #pragma unroll
                for (int j = 0; j < 4; j++) mma8(acc[i][j], af[i], bf[j]);
        }
        if (more) {
            STORE_TILE(cur ^ 1);
            __syncthreads();
            cur ^= 1;
        }
    }
    gemm_epilogue<XEPI>(acc, bias, resid, C, M, Nld, m0, n0, wm, wn, g, tg);
}

// ---- fused QKV (bf16 3-term): grid (12, 32) ---------------------------------
__global__ void __launch_bounds__(256, 2) qkv_kernel(
    const float* __restrict__ h,
    const float* __restrict__ wq, const float* __restrict__ bq,
    const float* __restrict__ wk, const float* __restrict__ bk,
    const float* __restrict__ wv, const float* __restrict__ bv)
{
    __shared__ __align__(16) uint32_t Hsm[2*HSTAGE];
    int x = blockIdx.x, m0 = blockIdx.y * BM;
    if (x < 8)
        gemm_core_bf16<0>(Hsm, h, wq, bq, nullptr, g_q, S, 1024, 1024, m0, x*128);
    else if (x < 10)
        gemm_core_bf16<0>(Hsm, h, wk, bk, nullptr, g_k, S, 256, 1024, m0, (x-8)*128);
    else
        gemm_core_bf16<0>(Hsm, h, wv, bv, nullptr, g_v, S, 256, 1024, m0, (x-10)*128);
}

// ---- O-proj + residual (bf16 3-term): grid (8, 32) --------------------------
__global__ void __launch_bounds__(256, 2) oproj_kernel(
    const float* __restrict__ wo, const float* __restrict__ bo,
    const float* __restrict__ x)
{
    __shared__ __align__(16) uint32_t Hsm[2*HSTAGE];
    gemm_core_bf16<1>(Hsm, g_attn, wo, bo, x, g_x1, S, 1024, 1024,
                      blockIdx.y*BM, blockIdx.x*BN);
}

// ---- MoE expert GEMMs (1xTF32, grouped, static 2-stage smem) ----------------
__global__ void __launch_bounds__(256, 2) moe1_kernel(
    const float* __restrict__ h2, const float* __restrict__ w1,
    const float* __restrict__ b1)
{
    int e = blockIdx.z;
    int M = g_cnt[e];
    int m0 = blockIdx.y * BM;
    if (m0 >= M) return;
    int o = g_off[e];
    __shared__ uint32_t sA[2*APLANE];
    __shared__ uint32_t sB[2*BPLANE];
    gemm_core_tf32<2,1>(sA, sB, h2, w1 + (size_t)e*1024*512, b1 + (size_t)e*512,
                        nullptr, g_hmid + (size_t)o*512, M, 512, 1024,
                        m0, blockIdx.x*BN, g_atok + o);
}

__global__ void __launch_bounds__(256, 2) moe2_kernel(
    const float* __restrict__ w2, const float* __restrict__ b2)
{
    int e = blockIdx.z;
    int M = g_cnt[e];
    int m0 = blockIdx.y * BM;
    if (m0 >= M) return;
    int o = g_off[e];
    __shared__ uint32_t sA[2*APLANE];
    __shared__ uint32_t sB[2*BPLANE];
    gemm_core_tf32<0,0>(sA, sB, g_hmid + (size_t)o*512, w2 + (size_t)e*512*1024,
                        b2 + (size_t)e*1024, nullptr, g_y + (size_t)o*1024,
                        M, 1024, 512, m0, blockIdx.x*BN, nullptr);
}

// ---------------- sliding-window attention, 1 warp = 1 query row ------------
__global__ void attn_kernel(const float* __restrict__ sinkp) {
    int warp = threadIdx.x >> 5, lane = threadIdx.x & 31;
    int i = blockIdx.x * 8 + warp;
    int h = blockIdx.y;
    int kvh = h >> 2;  // NH/NKV = 4
    const float scale = 0.08838834764831845f;  // 1/sqrt(128)

    float qr[4];
    const float* qp = g_q + (size_t)i * D + h * HD;
    #pragma unroll
    for (int c = 0; c < 4; c++) qr[c] = qp[lane + 32 * c];

    int jstart = (i >= (WS - 1)) ? (i - (WS - 1)) : 0;
    int cnt = i - jstart + 1;

    float s0 = -1e30f, s1 = -1e30f;
    for (int jj = 0; jj < cnt; ++jj) {
        const float* kp = g_k + (size_t)(jstart + jj) * (NKV * HD) + kvh * HD;
        float p = qr[0]*kp[lane] + qr[1]*kp[lane+32] + qr[2]*kp[lane+64] + qr[3]*kp[lane+96];
        #pragma unroll
        for (int s = 16; s; s >>= 1) p += __shfl_xor_sync(0xffffffffu, p, s);
        p *= scale;
        if ((jj & 31) == lane) { if (jj < 32) s0 = p; else s1 = p; }
    }
    float sink = *sinkp;
    float m = fmaxf(s0, s1);
    #pragma unroll
    for (int s = 16; s; s >>= 1) m = fmaxf(m, __shfl_xor_sync(0xffffffffu, m, s));
    m = fmaxf(m, sink);
    float e0 = expf(s0 - m), e1 = expf(s1 - m);
    float dsum = e0 + e1;
    #pragma unroll
    for (int s = 16; s; s >>= 1) dsum += __shfl_xor_sync(0xffffffffu, dsum, s);
    dsum += expf(sink - m);
    float inv = 1.f / dsum;

    float o0 = 0.f, o1 = 0.f, o2 = 0.f, o3 = 0.f;
    for (int jj = 0; jj < cnt; ++jj) {
        float pv = (jj < 32) ? e0 : e1;
        float p = __shfl_sync(0xffffffffu, pv, jj & 31);
        const float* vp = g_v + (size_t)(jstart + jj) * (NKV * HD) + kvh * HD;
        o0 += p * vp[lane];      o1 += p * vp[lane + 32];
        o2 += p * vp[lane + 64]; o3 += p * vp[lane + 96];
    }
    float* op = g_attn + (size_t)i * D + h * HD;
    op[lane]      = o0 * inv; op[lane + 32] = o1 * inv;
    op[lane + 64] = o2 * inv; op[lane + 96] = o3 * inv;
}

// ---------------- router: 1 warp = 1 token ----------------------------------
__global__ void router_kernel(const float* __restrict__ rw, const float* __restrict__ rb) {
    int warp = threadIdx.x >> 5, lane = threadIdx.x & 31;
    int t = blockIdx.x * 8 + warp;
    float acc[NE];
    #pragma unroll
    for (int e = 0; e < NE; e++) acc[e] = 0.f;
    const float* xr = g_h2 + (size_t)t * D;
    for (int d = lane; d < D; d += 32) {
        float xv = xr[d];
        const float* rr = rw + d * NE;
        #pragma unroll
        for (int e = 0; e < NE; e++) acc[e] += xv * rr[e];
    }
    #pragma unroll
    for (int e = 0; e < NE; e++) {
        float a = acc[e];
        #pragma unroll
        for (int s = 16; s; s >>= 1) a += __shfl_xor_sync(0xffffffffu, a, s);
        acc[e] = a;
    }
    if (lane == 0) {
        float logit[NE]; float m = -1e30f;
        #pragma unroll
        for (int e = 0; e < NE; e++) { logit[e] = (acc[e] + rb[e]) * 10.f; m = fmaxf(m, logit[e]); }
        float pe[NE]; float ssum = 0.f;
        #pragma unroll
        for (int e = 0; e < NE; e++) { pe[e] = expf(logit[e] - m); ssum += pe[e]; }
        float invs = 1.f / ssum;
        #pragma unroll
        for (int e = 0; e < NE; e++) g_probs[t * NE + e] = pe[e] * invs;
        int i0 = 0; float v0 = logit[0];
        #pragma unroll
        for (int e = 1; e < NE; e++) if (logit[e] > v0) { v0 = logit[e]; i0 = e; }
        int i1 = -1; float v1 = -1e30f;
        #pragma unroll
        for (int e = 0; e < NE; e++) if (e != i0 && logit[e] > v1) { v1 = logit[e]; i1 = e; }
        float ex = expf(v1 - v0);
        float w0 = 1.f / (1.f + ex);
        g_topi[t*2] = i0; g_topi[t*2+1] = i1;
        g_topw[t*2] = w0; g_topw[t*2+1] = 1.f - w0;
        atomicAdd(&g_cnt[i0], 1); atomicAdd(&g_cnt[i1], 1);
    }
}

__global__ void zero_kernel() {
    int t = threadIdx.x;
    if (t < NE) { g_cnt[t] = 0; g_cur[t] = 0; }
}

__global__ void offsets_kernel() {
    if (threadIdx.x == 0) {
        int s = 0;
        for (int e = 0; e < NE; e++) { g_off[e] = s; s += g_cnt[e]; }
    }
}

__global__ void place_kernel() {
    int t = blockIdx.x * blockDim.x + threadIdx.x;
    if (t >= S) return;
    #pragma unroll
    for (int k2 = 0; k2 < 2; k2++) {
        int e = g_topi[t*2 + k2];
        int slot = g_off[e] + atomicAdd(&g_cur[e], 1);
        g_atok[slot] = t;
        g_aw[slot] = g_topw[t*2 + k2];
        g_tslot[t*2 + k2] = slot;
    }
}

__global__ void colsum_kernel() {
    int e = blockIdx.x; int tid = threadIdx.x;
    float s = 0.f;
    for (int t = tid; t < S; t += 256) s += g_probs[t * NE + e];
    __shared__ float red[256];
    red[tid] = s; __syncthreads();
    for (int st = 128; st; st >>= 1) { if (tid < st) red[tid] += red[tid + st]; __syncthreads(); }
    if (tid == 0) g_colsum[e] = red[0];
}

__global__ void combine_kernel(float* __restrict__ out) {
    int t = blockIdx.x; int c = threadIdx.x;
    int s0 = g_tslot[t*2], s1 = g_tslot[t*2+1];
    float w0 = g_aw[s0], w1 = g_aw[s1];
    const float4* x14 = (const float4*)(g_x1 + (size_t)t * D);
    const float4* y0  = (const float4*)(g_y + (size_t)s0 * D);
    const float4* y1  = (const float4*)(g_y + (size_t)s1 * D);
    float4 a = x14[c], b = y0[c], d2 = y1[c];
    float4 o;
    o.x = a.x + w0*b.x + w1*d2.x; o.y = a.y + w0*b.y + w1*d2.y;
    o.z = a.z + w0*b.z + w1*d2.z; o.w = a.w + w0*b.w + w1*d2.w;
    ((float4*)out)[(size_t)t * (D/4) + c] = o;
}

__global__ void aux_kernel(float* __restrict__ out, int out_size) {
    int tid = threadIdx.x;
    float v = (tid < NE) ? g_colsum[tid] * g_colsum[tid] : 0.f;
    #pragma unroll
    for (int s = 16; s; s >>= 1) v += __shfl_xor_sync(0xffffffffu, v, s);
    if (tid == 0) {
        float aux = v * (1.0f / (float)NE) * 1e-5f;
        for (int idx = S * D; idx < out_size; ++idx) out[idx] = aux;
    }
}

// ---------------- launch -----------------------------------------------------
extern "C" void kernel_launch(void* const* d_in, const int* in_sizes, int n_in,
                              void* d_out, int out_size) {
    const float* x    = (const float*)d_in[0];
    const float* n1w  = (const float*)d_in[1];
    const float* wq   = (const float*)d_in[2];
    const float* bq   = (const float*)d_in[3];
    const float* wk   = (const float*)d_in[4];
    const float* bk   = (const float*)d_in[5];
    const float* wv   = (const float*)d_in[6];
    const float* bv   = (const float*)d_in[7];
    const float* wo   = (const float*)d_in[8];
    const float* bo   = (const float*)d_in[9];
    const float* sink = (const float*)d_in[10];
    const float* n2w  = (const float*)d_in[11];
    const float* rw   = (const float*)d_in[12];
    const float* rb   = (const float*)d_in[13];
    const float* w1   = (const float*)d_in[14];
    const float* b1   = (const float*)d_in[15];
    const float* w2   = (const float*)d_in[16];
    const float* b2   = (const float*)d_in[17];
    float* out = (float*)d_out;

    void* p;
    cudaGetSymbolAddress(&p, g_h);    float* hB    = (float*)p;
    cudaGetSymbolAddress(&p, g_x1);   float* x1B   = (float*)p;
    cudaGetSymbolAddress(&p, g_h2);   float* h2B   = (float*)p;

    // 1) RMSNorm1
    rmsnorm_kernel<<<S, 256>>>(x, n1w, hB);

    // 2) fused QKV projections (bf16x2 3-term tensor cores)
    qkv_kernel<<<dim3(12, 32), 256>>>(hB, wq, bq, wk, bk, wv, bv);

    // 3) sliding-window attention with sink
    attn_kernel<<<dim3(S/8, NH), 256>>>(sink);

    // 4) O-proj + residual (bf16x2 3-term)
    oproj_kernel<<<dim3(8, 32), 256>>>(wo, bo, x);

    // 5) RMSNorm2
    rmsnorm_kernel<<<S, 256>>>(x1B, n2w, h2B);

    // 6) router + grouping
    zero_kernel<<<1, 32>>>();
    router_kernel<<<S/8, 256>>>(rw, rb);
    offsets_kernel<<<1, 32>>>();
    place_kernel<<<8, 256>>>();
    colsum_kernel<<<NE, 256>>>();

    // 7) grouped MoE GEMMs (top-2 only, 1xTF32)
    moe1_kernel<<<dim3(4, 32, NE), 256>>>(h2B, w1, b1);
    moe2_kernel<<<dim3(8, 32, NE), 256>>>(w2, b2);

    // 8) combine + residual, aux loss
    combine_kernel<<<S, 256>>>(out);
    aux_kernel<<<1, 32>>>(out, out_size);
}